// round 10
// baseline (speedup 1.0000x reference)
#include <cuda_runtime.h>
#include <cstdint>
#include <math.h>

// ===========================================================================
// DTHyperNet via int8 IMMA digit-planes (mma.sync.m16n8k32.s8, s32 accum)
//   v = (rowmax/127) * (q1 + q2/254);  D = sA*sB*(P11 + (P12+P21)/254)
// 512-thread GEMM CTAs (16 warps, <=128 regs/thread) for 2x warps/SMSP.
// Weight quantization overlapped on a side stream.
// ===========================================================================

#define BQ 8192
#define FF 512
#define HH 512
#define CC 100
#define NNODES 15
#define NLEAVES 16
#define NFI 7680
#define NLC 1600
#define NLCP 1664
#define NSLICE 32
#define EPSV 1e-5f
#define INV254 (1.0f / 254.0f)

// -------------------- device scratch (no allocations allowed) --------------
__device__ int8_t g_qact[(size_t)BQ * 1024];
__device__ float  g_sact[BQ];
__device__ float  g_h0[(size_t)BQ * HH];
__device__ float  g_h1[(size_t)BQ * HH];
__device__ float  g_ht[(size_t)BQ * HH];
__device__ int8_t g_qwi[(size_t)HH * 1024];
__device__ int8_t g_qw1[(size_t)2 * HH * 1024];
__device__ int8_t g_qw2[(size_t)2 * HH * 1024];
__device__ int8_t g_qwfi[(size_t)NFI * 1024];
__device__ int8_t g_qwfs[(size_t)NFI * 1024];
__device__ int8_t g_qwlc[(size_t)NLCP * 1024];
__device__ float  g_swi[HH], g_sw1[2 * HH], g_sw2[2 * HH];
__device__ float  g_swfi[NFI], g_swfs[NFI], g_swlc[NLCP];
__device__ float  g_lc[(size_t)BQ * NLC];
__device__ float  g_pse[(size_t)BQ * NNODES * NSLICE];
__device__ float  g_psx[(size_t)BQ * NNODES * NSLICE];
__device__ float  g_psf[(size_t)BQ * NNODES * NSLICE];

// -------------------- PTX helpers (sm_80 baseline only) --------------------
__device__ __forceinline__ uint32_t smem_u32(const void* p) {
    uint32_t a;
    asm("{ .reg .u64 t; cvta.to.shared.u64 t, %1; cvt.u32.u64 %0, t; }"
        : "=r"(a) : "l"(p));
    return a;
}
#define CP16(dst, src) \
    asm volatile("cp.async.cg.shared.global [%0], [%1], 16;" :: "r"(dst), "l"(src))
#define CP_COMMIT() asm volatile("cp.async.commit_group;" ::: "memory")
#define CP_WAIT0() asm volatile("cp.async.wait_group 0;" ::: "memory")
#define CP_WAIT1() asm volatile("cp.async.wait_group 1;" ::: "memory")

__device__ __forceinline__ void ldsm4(uint32_t* r, uint32_t addr) {
    asm volatile("ldmatrix.sync.aligned.m8n8.x4.shared.b16 {%0,%1,%2,%3}, [%4];"
                 : "=r"(r[0]), "=r"(r[1]), "=r"(r[2]), "=r"(r[3]) : "r"(addr));
}
__device__ __forceinline__ void mma_s8(int* c, const uint32_t* a,
                                       uint32_t b0, uint32_t b1) {
    asm volatile(
        "mma.sync.aligned.m16n8k32.row.col.s32.s8.s8.s32 "
        "{%0,%1,%2,%3}, {%4,%5,%6,%7}, {%8,%9}, {%0,%1,%2,%3};"
        : "+r"(c[0]), "+r"(c[1]), "+r"(c[2]), "+r"(c[3])
        : "r"(a[0]), "r"(a[1]), "r"(a[2]), "r"(a[3]), "r"(b0), "r"(b1));
}

#define ROWB 80
#define TILEB (128 * ROWB)          // 10240
#define TILEA64 (64 * ROWB)         // 5120
#define NSTAGE 3
#define KSTAGES 24                  // 1536 bytes / 64
#define PASS1 8
#define SMEM_G (NSTAGE * 2 * TILEB)            // 61440
#define FSTAGE (TILEA64 + 2 * TILEB)           // 25600
#define SMEM_F (NSTAGE * FSTAGE)               // 76800

// ===========================================================================
// Generic int8 GEMM: 512 thr, 16 warps (4x4), 32x32 warp tiles, 128x128 CTA.
// ===========================================================================
template <int EPI>
__global__ __launch_bounds__(512) void gemm_i8(
    const int8_t* __restrict__ qA, const float* __restrict__ sA,
    const int8_t* __restrict__ qB, const float* __restrict__ sB,
    float* __restrict__ C, int Nout,
    const float* __restrict__ bias, const float* __restrict__ gamma,
    const float* __restrict__ beta, const float* __restrict__ resid)
{
    extern __shared__ char dsm[];
    const uint32_t sb = smem_u32(dsm);

    const int tid = threadIdx.x;
    const int lane = tid & 31;
    const int wid = tid >> 5;
    const int warp_m = wid >> 2;      // 0..3
    const int warp_n = wid & 3;       // 0..3
    const int bm = blockIdx.y * 128;
    const int bn = blockIdx.x * 128;

    const int8_t* Asrc[3] = { qA + (size_t)bm * 1024,
                              qA + (size_t)bm * 1024,
                              qA + (size_t)bm * 1024 + 512 };
    const int8_t* Bsrc[3] = { qB + (size_t)bn * 1024,
                              qB + (size_t)bn * 1024 + 512,
                              qB + (size_t)bn * 1024 };

    const int arow = (lane & 7) + ((lane >> 3) & 1) * 8;
    const int asel = lane >> 4;
    const int brow = ((lane >> 4) & 1) * 8 + (lane & 7);
    const int bsel = (lane >> 3) & 1;
    const uint32_t a_lane = (uint32_t)(warp_m * 32 + arow) * ROWB;
    const uint32_t b_lane = (uint32_t)(warp_n * 32 + brow) * ROWB;

    int acc0[2][4][4], acc1[2][4][4];
#pragma unroll
    for (int i = 0; i < 2; i++)
#pragma unroll
        for (int j = 0; j < 4; j++)
#pragma unroll
            for (int u = 0; u < 4; u++) { acc0[i][j][u] = 0; acc1[i][j][u] = 0; }

    auto load_stage = [&](int s, int buf) {
        const int p = s >> 3;
        const int ko = (s & 7) * 64;
        const uint32_t ab = sb + buf * (2 * TILEB);
        const uint32_t bb = ab + TILEB;
        const int r = tid >> 2, c = (tid & 3) * 16;     // 512 chunks each
        CP16(ab + r * ROWB + c, Asrc[p] + ko + (size_t)r * 1024 + c);
        CP16(bb + r * ROWB + c, Bsrc[p] + ko + (size_t)r * 1024 + c);
    };

    load_stage(0, 0); CP_COMMIT();
    load_stage(1, 1); CP_COMMIT();

    int buf = 0;
    auto stage_body = [&](int s, int (&acc)[2][4][4]) {
        if (s + 2 < KSTAGES) { CP_WAIT1(); } else { CP_WAIT0(); }
        __syncthreads();
        if (s + 2 < KSTAGES) {
            int nb = buf + 2; if (nb >= NSTAGE) nb -= NSTAGE;
            load_stage(s + 2, nb);
            CP_COMMIT();
        }
        const uint32_t ab = sb + buf * (2 * TILEB);
        const uint32_t bb = ab + TILEB;
#pragma unroll
        for (int kh = 0; kh < 2; kh++) {
            uint32_t af[2][4], bf[2][4];
            const uint32_t kadd = kh * 32;
#pragma unroll
            for (int m = 0; m < 2; m++)
                ldsm4(af[m], ab + a_lane + m * (16 * ROWB) + kadd + asel * 16);
#pragma unroll
            for (int n2 = 0; n2 < 2; n2++)
                ldsm4(bf[n2], bb + b_lane + n2 * (16 * ROWB) + kadd + bsel * 16);
#pragma unroll
            for (int m = 0; m < 2; m++)
#pragma unroll
                for (int n = 0; n < 4; n++)
                    mma_s8(acc[m][n], af[m],
                           bf[n >> 1][(n & 1) * 2 + 0], bf[n >> 1][(n & 1) * 2 + 1]);
        }
        buf++; if (buf == NSTAGE) buf = 0;
    };

    for (int s = 0; s < PASS1; s++) stage_body(s, acc0);
    for (int s = PASS1; s < KSTAGES; s++) stage_body(s, acc1);

    // -------- epilogue --------
    const float RS = rsqrtf(1.0f + EPSV);
    const int lm = lane >> 2;
    const int ln2 = (lane & 3) * 2;
    const int row0 = bm + warp_m * 32;
    const int col0 = bn + warp_n * 32;

#pragma unroll
    for (int m = 0; m < 2; m++) {
        const int r_lo = row0 + m * 16 + lm;
        const int r_hi = r_lo + 8;
        const float sa0 = sA[r_lo], sa1 = sA[r_hi];
#pragma unroll
        for (int n = 0; n < 4; n++) {
            const int gn = col0 + n * 8 + ln2;
            if (EPI == 0 && gn >= Nout) continue;
            const float sb0 = sB[gn], sb1 = sB[gn + 1];
            const int* c0 = acc0[m][n];
            const int* c1 = acc1[m][n];
            float v[4];
            v[0] = ((float)c0[0] + (float)c1[0] * INV254) * (sa0 * sb0);
            v[1] = ((float)c0[1] + (float)c1[1] * INV254) * (sa0 * sb1);
            v[2] = ((float)c0[2] + (float)c1[2] * INV254) * (sa1 * sb0);
            v[3] = ((float)c0[3] + (float)c1[3] * INV254) * (sa1 * sb1);
            const float bz0 = bias[gn], bz1 = bias[gn + 1];
            if (EPI == 0) {
                *(float2*)(C + (size_t)r_lo * Nout + gn) = make_float2(v[0] + bz0, v[1] + bz1);
                *(float2*)(C + (size_t)r_hi * Nout + gn) = make_float2(v[2] + bz0, v[3] + bz1);
            } else {
                const float s0 = gamma[gn] * RS, s1 = gamma[gn + 1] * RS;
                const float e0 = beta[gn], e1 = beta[gn + 1];
                v[0] = (v[0] + bz0) * s0 + e0; v[1] = (v[1] + bz1) * s1 + e1;
                v[2] = (v[2] + bz0) * s0 + e0; v[3] = (v[3] + bz1) * s1 + e1;
#pragma unroll
                for (int u = 0; u < 4; u++) {
                    if (EPI == 1) v[u] = fmaxf(v[u], 0.0f);
                    else v[u] = 0.5f * v[u] * (1.0f + erff(v[u] * 0.70710678118654752f));
                }
                if (EPI == 3) {
                    const float2 r0 = *(const float2*)(resid + (size_t)r_lo * HH + gn);
                    const float2 r1 = *(const float2*)(resid + (size_t)r_hi * HH + gn);
                    v[0] += r0.x; v[1] += r0.y; v[2] += r1.x; v[3] += r1.y;
                }
                *(float2*)(C + (size_t)r_lo * HH + gn) = make_float2(v[0], v[1]);
                *(float2*)(C + (size_t)r_hi * HH + gn) = make_float2(v[2], v[3]);
            }
        }
    }
}

// ===========================================================================
// Fused int8 fi/fs head + node reduction. 64x128 CTA, 512 thr, 16 warps
// (2x8), 32x16 warp tiles, dual-function dual-plane. grid (60, 128).
// ===========================================================================
__global__ __launch_bounds__(512, 1) void gemm_fifs_i8(
    const int8_t* __restrict__ qA, const float* __restrict__ sA,
    const int8_t* __restrict__ qBi, const float* __restrict__ sBi,
    const int8_t* __restrict__ qBs, const float* __restrict__ sBs,
    const float* __restrict__ x,
    const float* __restrict__ b_fi, const float* __restrict__ b_fs,
    float* __restrict__ pse, float* __restrict__ psx, float* __restrict__ psf)
{
    extern __shared__ char dsm[];
    const uint32_t sb = smem_u32(dsm);

    const int tid = threadIdx.x;
    const int lane = tid & 31;
    const int wid = tid >> 5;
    const int warp_m = wid >> 3;      // 0..1 (32-row slice)
    const int warp_n = wid & 7;       // 0..7 (16-col slice)
    const int ct = blockIdx.x;
    const int bm = blockIdx.y * 64;
    const int bn = ct * 128;
    const int node = ct >> 2;
    const int slice = (ct & 3) * 8 + warp_n;              // 0..31
    const int xbase = (ct & 3) * 128 + warp_n * 16;

    const int8_t* Asrc[3] = { qA + (size_t)bm * 1024,
                              qA + (size_t)bm * 1024,
                              qA + (size_t)bm * 1024 + 512 };
    const int8_t* BiP[3] = { qBi + (size_t)bn * 1024,
                             qBi + (size_t)bn * 1024 + 512,
                             qBi + (size_t)bn * 1024 };
    const int8_t* BsP[3] = { qBs + (size_t)bn * 1024,
                             qBs + (size_t)bn * 1024 + 512,
                             qBs + (size_t)bn * 1024 };

    const int arow = (lane & 7) + ((lane >> 3) & 1) * 8;
    const int asel = lane >> 4;
    const int brow = ((lane >> 4) & 1) * 8 + (lane & 7);
    const int bsel = (lane >> 3) & 1;
    const uint32_t a_lane = (uint32_t)(warp_m * 32 + arow) * ROWB;
    const uint32_t b_lane = (uint32_t)(warp_n * 16 + brow) * ROWB;

    int aI0[2][2][4], aI1[2][2][4], aS0[2][2][4], aS1[2][2][4];
#pragma unroll
    for (int i = 0; i < 2; i++)
#pragma unroll
        for (int j = 0; j < 2; j++)
#pragma unroll
            for (int u = 0; u < 4; u++) {
                aI0[i][j][u] = 0; aI1[i][j][u] = 0;
                aS0[i][j][u] = 0; aS1[i][j][u] = 0;
            }

    auto load_stage = [&](int s, int buf) {
        const int p = s >> 3;
        const int ko = (s & 7) * 64;
        const uint32_t ab = sb + buf * FSTAGE;
        const uint32_t ib = ab + TILEA64;
        const uint32_t qb = ib + TILEB;
        if (tid < 256) {   // A: 64 rows x 64B = 256 chunks
            const int r = tid >> 2, c = (tid & 3) * 16;
            CP16(ab + r * ROWB + c, Asrc[p] + ko + (size_t)r * 1024 + c);
        }
        {                  // B tiles: 512 chunks each, 1/thread
            const int r = tid >> 2, c = (tid & 3) * 16;
            CP16(ib + r * ROWB + c, BiP[p] + ko + (size_t)r * 1024 + c);
            CP16(qb + r * ROWB + c, BsP[p] + ko + (size_t)r * 1024 + c);
        }
    };

    load_stage(0, 0); CP_COMMIT();
    load_stage(1, 1); CP_COMMIT();

    int buf = 0;
    auto stage_body = [&](int s, int (&aI)[2][2][4], int (&aS)[2][2][4]) {
        if (s + 2 < KSTAGES) { CP_WAIT1(); } else { CP_WAIT0(); }
        __syncthreads();
        if (s + 2 < KSTAGES) {
            int nb = buf + 2; if (nb >= NSTAGE) nb -= NSTAGE;
            load_stage(s + 2, nb);
            CP_COMMIT();
        }
        const uint32_t ab = sb + buf * FSTAGE;
        const uint32_t ib = ab + TILEA64;
        const uint32_t qb = ib + TILEB;
#pragma unroll
        for (int kh = 0; kh < 2; kh++) {
            uint32_t af[2][4], bi[4], bq[4];
            const uint32_t kadd = kh * 32;
#pragma unroll
            for (int m = 0; m < 2; m++)
                ldsm4(af[m], ab + a_lane + m * (16 * ROWB) + kadd + asel * 16);
            ldsm4(bi, ib + b_lane + kadd + bsel * 16);
            ldsm4(bq, qb + b_lane + kadd + bsel * 16);
#pragma unroll
            for (int m = 0; m < 2; m++)
#pragma unroll
                for (int n = 0; n < 2; n++) {
                    mma_s8(aI[m][n], af[m], bi[n * 2 + 0], bi[n * 2 + 1]);
                    mma_s8(aS[m][n], af[m], bq[n * 2 + 0], bq[n * 2 + 1]);
                }
        }
        buf++; if (buf == NSTAGE) buf = 0;
    };

    for (int s = 0; s < PASS1; s++) stage_body(s, aI0, aS0);
    for (int s = PASS1; s < KSTAGES; s++) stage_body(s, aI1, aS1);

    // -------- fused reduction epilogue --------
    const int lm = lane >> 2;
    const int ln2 = (lane & 3) * 2;
    const int row0 = bm + warp_m * 32;
    const int col0 = bn + warp_n * 16;

    float sa[2][2];
#pragma unroll
    for (int m = 0; m < 2; m++) {
        sa[m][0] = sA[row0 + m * 16 + lm];
        sa[m][1] = sA[row0 + m * 16 + lm + 8];
    }

    float se[4], sx[4], sf[4];
#pragma unroll
    for (int i = 0; i < 4; i++) { se[i] = 0.f; sx[i] = 0.f; sf[i] = 0.f; }

#pragma unroll
    for (int n = 0; n < 2; n++) {
        const int gn = col0 + n * 8 + ln2;
        const int xc = xbase + n * 8 + ln2;
        const float bi0 = b_fi[gn], bi1 = b_fi[gn + 1];
        const float bs0 = b_fs[gn], bs1 = b_fs[gn + 1];
        const float si0 = sBi[gn], si1 = sBi[gn + 1];
        const float ss0 = sBs[gn], ss1 = sBs[gn + 1];
#pragma unroll
        for (int m = 0; m < 2; m++) {
            const int r_lo = row0 + m * 16 + lm;
            const int r_hi = r_lo + 8;
            const int* i0 = aI0[m][n]; const int* i1 = aI1[m][n];
            const int* s0 = aS0[m][n]; const int* s1 = aS1[m][n];
            const float fi0 = ((float)i0[0] + (float)i1[0] * INV254) * (sa[m][0] * si0) + bi0;
            const float fi1 = ((float)i0[1] + (float)i1[1] * INV254) * (sa[m][0] * si1) + bi1;
            const float fi2 = ((float)i0[2] + (float)i1[2] * INV254) * (sa[m][1] * si0) + bi0;
            const float fi3 = ((float)i0[3] + (float)i1[3] * INV254) * (sa[m][1] * si1) + bi1;
            const float fs0 = ((float)s0[0] + (float)s1[0] * INV254) * (sa[m][0] * ss0) + bs0;
            const float fs1 = ((float)s0[1] + (float)s1[1] * INV254) * (sa[m][0] * ss1) + bs1;
            const float fs2 = ((float)s0[2] + (float)s1[2] * INV254) * (sa[m][1] * ss0) + bs0;
            const float fs3 = ((float)s0[3] + (float)s1[3] * INV254) * (sa[m][1] * ss1) + bs1;
            const float e0 = __expf(fi0);
            const float e1 = __expf(fi1);
            const float e2 = __expf(fi2);
            const float e3 = __expf(fi3);
            const float2 x0 = *(const float2*)(x + (size_t)r_lo * FF + xc);
            const float2 x1 = *(const float2*)(x + (size_t)r_hi * FF + xc);
            se[m * 2 + 0] += e0 + e1;
            se[m * 2 + 1] += e2 + e3;
            sx[m * 2 + 0] += e0 * x0.x + e1 * x0.y;
            sx[m * 2 + 1] += e2 * x1.x + e3 * x1.y;
            sf[m * 2 + 0] += e0 * fs0 + e1 * fs1;
            sf[m * 2 + 1] += e2 * fs2 + e3 * fs3;
        }
    }

#pragma unroll
    for (int i = 0; i < 4; i++) {
        se[i] += __shfl_xor_sync(0xffffffffu, se[i], 1);
        se[i] += __shfl_xor_sync(0xffffffffu, se[i], 2);
        sx[i] += __shfl_xor_sync(0xffffffffu, sx[i], 1);
        sx[i] += __shfl_xor_sync(0xffffffffu, sx[i], 2);
        sf[i] += __shfl_xor_sync(0xffffffffu, sf[i], 1);
        sf[i] += __shfl_xor_sync(0xffffffffu, sf[i], 2);
    }
    if ((lane & 3) == 0) {
#pragma unroll
        for (int i = 0; i < 4; i++) {
            const int row = row0 + (i >> 1) * 16 + lm + (i & 1) * 8;
            const size_t o = ((size_t)row * NNODES + node) * NSLICE + slice;
            pse[o] = se[i]; psx[o] = sx[i]; psf[o] = sf[i];
        }
    }
}

// ---------------- per-row two-plane int8 quantization of activations --------
__global__ __launch_bounds__(256) void quant_act(
    const float* __restrict__ src, int8_t* __restrict__ q, float* __restrict__ s)
{
    const int row = blockIdx.x * 8 + (threadIdx.x >> 5);
    const int lane = threadIdx.x & 31;
    const float4* rp = (const float4*)(src + (size_t)row * 512);

    float4 v[4];
    float m = 0.0f;
#pragma unroll
    for (int i = 0; i < 4; i++) {
        v[i] = rp[i * 32 + lane];
        m = fmaxf(m, fmaxf(fmaxf(fabsf(v[i].x), fabsf(v[i].y)),
                           fmaxf(fabsf(v[i].z), fabsf(v[i].w))));
    }
#pragma unroll
    for (int o = 16; o > 0; o >>= 1)
        m = fmaxf(m, __shfl_xor_sync(0xffffffffu, m, o));

    const float inv = (m > 0.0f) ? 127.0f / m : 0.0f;
    if (lane == 0) s[row] = m * (1.0f / 127.0f);

    int8_t* q1p = q + (size_t)row * 1024;
    int8_t* q2p = q1p + 512;
#pragma unroll
    for (int i = 0; i < 4; i++) {
        const float* f = &v[i].x;
        char4 c1, c2;
        signed char* p1 = &c1.x;
        signed char* p2 = &c2.x;
#pragma unroll
        for (int u = 0; u < 4; u++) {
            const float t = f[u] * inv;
            const float a = rintf(t);
            const float b = rintf((t - a) * 254.0f);
            p1[u] = (signed char)(int)a;
            p2[u] = (signed char)(int)b;
        }
        ((char4*)q1p)[i * 32 + lane] = c1;
        ((char4*)q2p)[i * 32 + lane] = c2;
    }
}

// ---------------- transpose + per-column two-plane int8 weight quant --------
__global__ __launch_bounds__(256) void quant_w(
    const float* __restrict__ W, int8_t* __restrict__ q, float* __restrict__ s, int N)
{
    __shared__ float wm[8][32];
    __shared__ float invs[32];
    __shared__ int8_t qs[32][1040];

    const int n0 = blockIdx.x * 32;
    const int tx = threadIdx.x & 31;
    const int wy = threadIdx.x >> 5;
    const int n = n0 + tx;
    const bool ok = n < N;

    float m = 0.0f;
    for (int k = wy; k < 512; k += 8) {
        const float v = ok ? W[(size_t)k * N + n] : 0.0f;
        m = fmaxf(m, fabsf(v));
    }
    wm[wy][tx] = m;
    __syncthreads();
    if (threadIdx.x < 32) {
        float mm = wm[0][threadIdx.x];
#pragma unroll
        for (int w = 1; w < 8; w++) mm = fmaxf(mm, wm[w][threadIdx.x]);
        invs[threadIdx.x] = (mm > 0.0f) ? 127.0f / mm : 0.0f;
        s[n0 + threadIdx.x] = mm * (1.0f / 127.0f);
    }
    __syncthreads();

    const float inv = invs[tx];
    for (int k = wy; k < 512; k += 8) {
        const float v = ok ? W[(size_t)k * N + n] : 0.0f;
        const float t = v * inv;
        const float a = rintf(t);
        const float b = rintf((t - a) * 254.0f);
        qs[tx][k] = (int8_t)(int)a;
        qs[tx][512 + k] = (int8_t)(int)b;
    }
    __syncthreads();

#pragma unroll
    for (int i = 0; i < 8; i++) {
        const int idx = threadIdx.x + i * 256;
        const int row = idx >> 6;
        const int c = (idx & 63) * 16;
        *(uint4*)(q + (size_t)(n0 + row) * 1024 + c) = *(uint4*)(&qs[row][c]);
    }
}

// ---------------- sd + tree combine -----------------------------------------
__global__ __launch_bounds__(128) void sd_combine_kernel(
    const float* __restrict__ pse, const float* __restrict__ psx,
    const float* __restrict__ psf, const float* __restrict__ lnc,
    float* __restrict__ out)
{
    __shared__ float s_sd[NNODES];
    __shared__ float coeff[NLEAVES];
    const int b = blockIdx.x;
    const int tid = threadIdx.x;

    if (tid < NNODES) {
        const size_t base = ((size_t)b * NNODES + tid) * NSLICE;
        float se = 0.f, sx = 0.f, sf = 0.f;
#pragma unroll
        for (int q = 0; q < NSLICE; q++) {
            se += pse[base + q]; sx += psx[base + q]; sf += psf[base + q];
        }
        const float z = (sx - sf) / se;
        s_sd[tid] = 1.0f / (1.0f + expf(-z));
    }
    __syncthreads();
    if (tid < NLEAVES) {
        const int l = tid;
        float p, c;
        p = s_sd[0];            c  = ((l >> 3) & 1) ? 1.0f - p : p;
        p = s_sd[1 + (l >> 3)]; c *= ((l >> 2) & 1) ? 1.0f - p : p;
        p = s_sd[3 + (l >> 2)]; c *= ((l >> 1) & 1) ? 1.0f - p : p;
        p = s_sd[7 + (l >> 1)]; c *= (l & 1)        ? 1.0f - p : p;
        coeff[l] = c;
    }
    __syncthreads();
    if (tid < CC) {
        const float* lp = lnc + (size_t)b * (NLEAVES * CC) + tid;
        float acc = 0.0f;
#pragma unroll
        for (int l = 0; l < NLEAVES; l++) acc += coeff[l] * lp[l * CC];
        out[b * CC + tid] = acc;
    }
}

// ===========================================================================
extern "C" void kernel_launch(void* const* d_in, const int* in_sizes, int n_in,
                              void* d_out, int out_size)
{
    const float* x    = (const float*)d_in[0];
    const float* w_in = (const float*)d_in[1];
    const float* b_in = (const float*)d_in[2];
    const float* g0   = (const float*)d_in[3];
    const float* be0  = (const float*)d_in[4];
    const float* bw1  = (const float*)d_in[5];
    const float* bb1  = (const float*)d_in[6];
    const float* bg1  = (const float*)d_in[7];
    const float* bbe1 = (const float*)d_in[8];
    const float* bw2  = (const float*)d_in[9];
    const float* bb2  = (const float*)d_in[10];
    const float* bg2  = (const float*)d_in[11];
    const float* bbe2 = (const float*)d_in[12];
    const float* w_fi = (const float*)d_in[13];
    const float* b_fi = (const float*)d_in[14];
    const float* w_fs = (const float*)d_in[15];
    const float* b_fs = (const float*)d_in[16];
    const float* w_lc = (const float*)d_in[17];
    const float* b_lc = (const float*)d_in[18];
    float* out = (float*)d_out;

    int8_t *qact, *qwi, *qw1, *qw2, *qwfi, *qwfs, *qwlc;
    float *sact, *swi, *sw1, *sw2, *swfi, *swfs, *swlc;
    float *h0, *h1, *ht, *lc, *pse, *psx, *psf;
    cudaGetSymbolAddress((void**)&qact, g_qact); cudaGetSymbolAddress((void**)&sact, g_sact);
    cudaGetSymbolAddress((void**)&qwi, g_qwi);   cudaGetSymbolAddress((void**)&swi, g_swi);
    cudaGetSymbolAddress((void**)&qw1, g_qw1);   cudaGetSymbolAddress((void**)&sw1, g_sw1);
    cudaGetSymbolAddress((void**)&qw2, g_qw2);   cudaGetSymbolAddress((void**)&sw2, g_sw2);
    cudaGetSymbolAddress((void**)&qwfi, g_qwfi); cudaGetSymbolAddress((void**)&swfi, g_swfi);
    cudaGetSymbolAddress((void**)&qwfs, g_qwfs); cudaGetSymbolAddress((void**)&swfs, g_swfs);
    cudaGetSymbolAddress((void**)&qwlc, g_qwlc); cudaGetSymbolAddress((void**)&swlc, g_swlc);
    cudaGetSymbolAddress((void**)&h0, g_h0);     cudaGetSymbolAddress((void**)&h1, g_h1);
    cudaGetSymbolAddress((void**)&ht, g_ht);     cudaGetSymbolAddress((void**)&lc, g_lc);
    cudaGetSymbolAddress((void**)&pse, g_pse);
    cudaGetSymbolAddress((void**)&psx, g_psx);
    cudaGetSymbolAddress((void**)&psf, g_psf);

    cudaFuncSetAttribute(gemm_i8<0>, cudaFuncAttributeMaxDynamicSharedMemorySize, SMEM_G);
    cudaFuncSetAttribute(gemm_i8<1>, cudaFuncAttributeMaxDynamicSharedMemorySize, SMEM_G);
    cudaFuncSetAttribute(gemm_i8<2>, cudaFuncAttributeMaxDynamicSharedMemorySize, SMEM_G);
    cudaFuncSetAttribute(gemm_i8<3>, cudaFuncAttributeMaxDynamicSharedMemorySize, SMEM_G);
    cudaFuncSetAttribute(gemm_fifs_i8, cudaFuncAttributeMaxDynamicSharedMemorySize, SMEM_F);

    const dim3 g512(HH / 128, BQ / 128);
    const dim3 gfi(NFI / 128, BQ / 64);
    const dim3 glc(NLCP / 128, BQ / 128);
    const int QAB = BQ / 8;

    // ---- side stream for weight quantization (overlaps the GEMM chain) ----
    cudaStream_t s2;
    cudaStreamCreateWithFlags(&s2, cudaStreamNonBlocking);
    cudaEvent_t evFork, evA, evB, evC, evD, evE, evF;
    cudaEventCreateWithFlags(&evFork, cudaEventDisableTiming);
    cudaEventCreateWithFlags(&evA, cudaEventDisableTiming);
    cudaEventCreateWithFlags(&evB, cudaEventDisableTiming);
    cudaEventCreateWithFlags(&evC, cudaEventDisableTiming);
    cudaEventCreateWithFlags(&evD, cudaEventDisableTiming);
    cudaEventCreateWithFlags(&evE, cudaEventDisableTiming);
    cudaEventCreateWithFlags(&evF, cudaEventDisableTiming);

    cudaEventRecord(evFork, 0);
    cudaStreamWaitEvent(s2, evFork, 0);

    quant_act<<<QAB, 256>>>(x, qact, sact);
    quant_w<<<HH / 32, 256, 0, s2>>>(w_in, qwi, swi, HH);
    cudaEventRecord(evA, s2);
    quant_w<<<HH / 32, 256, 0, s2>>>(bw1, qw1, sw1, HH);
    cudaEventRecord(evB, s2);
    cudaStreamWaitEvent(0, evA, 0);
    gemm_i8<1><<<g512, 512, SMEM_G>>>(qact, sact, qwi, swi,
        h0, HH, b_in, g0, be0, nullptr);
    quant_act<<<QAB, 256>>>(h0, qact, sact);
    quant_w<<<HH / 32, 256, 0, s2>>>(bw2, qw2, sw2, HH);
    cudaEventRecord(evC, s2);
    quant_w<<<HH / 32, 256, 0, s2>>>(bw1 + HH * HH, qw1 + (size_t)HH * 1024, sw1 + HH, HH);
    cudaEventRecord(evD, s2);
    quant_w<<<HH / 32, 256, 0, s2>>>(bw2 + HH * HH, qw2 + (size_t)HH * 1024, sw2 + HH, HH);
    cudaEventRecord(evE, s2);
    quant_w<<<NFI / 32, 256, 0, s2>>>(w_fi, qwfi, swfi, NFI);
    quant_w<<<NFI / 32, 256, 0, s2>>>(w_fs, qwfs, swfs, NFI);
    quant_w<<<NLCP / 32, 256, 0, s2>>>(w_lc, qwlc, swlc, NLC);
    cudaEventRecord(evF, s2);

    cudaStreamWaitEvent(0, evB, 0);
    gemm_i8<2><<<g512, 512, SMEM_G>>>(qact, sact, qw1, sw1,
        ht, HH, bb1, bg1, bbe1, nullptr);
    quant_act<<<QAB, 256>>>(ht, qact, sact);
    cudaStreamWaitEvent(0, evC, 0);
    gemm_i8<3><<<g512, 512, SMEM_G>>>(qact, sact, qw2, sw2,
        h1, HH, bb2, bg2, bbe2, h0);
    quant_act<<<QAB, 256>>>(h1, qact, sact);
    cudaStreamWaitEvent(0, evD, 0);
    gemm_i8<2><<<g512, 512, SMEM_G>>>(qact, sact, qw1 + (size_t)HH * 1024, sw1 + HH,
        ht, HH, bb1 + HH, bg1 + HH, bbe1 + HH, nullptr);
    quant_act<<<QAB, 256>>>(ht, qact, sact);
    cudaStreamWaitEvent(0, evE, 0);
    gemm_i8<3><<<g512, 512, SMEM_G>>>(qact, sact, qw2 + (size_t)HH * 1024, sw2 + HH,
        h0, HH, bb2 + HH, bg2 + HH, bbe2 + HH, h1);
    quant_act<<<QAB, 256>>>(h0, qact, sact);
    cudaStreamWaitEvent(0, evF, 0);
    gemm_fifs_i8<<<gfi, 512, SMEM_F>>>(qact, sact, qwfi, swfi, qwfs, swfs,
                                       x, b_fi, b_fs, pse, psx, psf);
    gemm_i8<0><<<glc, 512, SMEM_G>>>(qact, sact, qwlc, swlc,
        lc, NLC, b_lc, nullptr, nullptr, nullptr);
    sd_combine_kernel<<<BQ, 128>>>(pse, psx, psf, lc, out);
}

// round 12
// speedup vs baseline: 1.1472x; 1.1472x over previous
#include <cuda_runtime.h>
#include <cstdint>
#include <math.h>

// ===========================================================================
// DTHyperNet via int8 IMMA digit-planes (mma.sync.m16n8k32.s8, s32 accum)
//   v = (rowmax/127) * (q1 + q2/254);  D = sA*sB*(P11 + (P12+P21)/254)
// Legacy-mma dispatch is the floor (~16cyc/SMSP/mma); this version halves the
// pipeline stage count (128B K-chunks) and overlaps lc with fifs.
// ===========================================================================

#define BQ 8192
#define FF 512
#define HH 512
#define CC 100
#define NNODES 15
#define NLEAVES 16
#define NFI 7680
#define NLC 1600
#define NLCP 1664
#define EPSV 1e-5f
#define INV254 (1.0f / 254.0f)

// -------------------- device scratch (no allocations allowed) --------------
__device__ int8_t g_qact[(size_t)BQ * 1024];
__device__ float  g_sact[BQ];
__device__ float  g_h0[(size_t)BQ * HH];
__device__ float  g_h1[(size_t)BQ * HH];
__device__ float  g_ht[(size_t)BQ * HH];
__device__ int8_t g_qwi[(size_t)HH * 1024];
__device__ int8_t g_qw1[(size_t)2 * HH * 1024];
__device__ int8_t g_qw2[(size_t)2 * HH * 1024];
__device__ int8_t g_qwfi[(size_t)NFI * 1024];
__device__ int8_t g_qwfs[(size_t)NFI * 1024];
__device__ int8_t g_qwlc[(size_t)NLCP * 1024];
__device__ float  g_swi[HH], g_sw1[2 * HH], g_sw2[2 * HH];
__device__ float  g_swfi[NFI], g_swfs[NFI], g_swlc[NLCP];
__device__ float  g_lc[(size_t)BQ * NLC];
__device__ float  g_pse[(size_t)BQ * NNODES * 16];
__device__ float  g_psx[(size_t)BQ * NNODES * 16];
__device__ float  g_psf[(size_t)BQ * NNODES * 16];

// -------------------- PTX helpers (sm_80 baseline only) --------------------
__device__ __forceinline__ uint32_t smem_u32(const void* p) {
    uint32_t a;
    asm("{ .reg .u64 t; cvta.to.shared.u64 t, %1; cvt.u32.u64 %0, t; }"
        : "=r"(a) : "l"(p));
    return a;
}
#define CP16(dst, src) \
    asm volatile("cp.async.cg.shared.global [%0], [%1], 16;" :: "r"(dst), "l"(src))
#define CP_COMMIT() asm volatile("cp.async.commit_group;" ::: "memory")
#define CP_WAIT0() asm volatile("cp.async.wait_group 0;" ::: "memory")
#define CP_WAIT1() asm volatile("cp.async.wait_group 1;" ::: "memory")

__device__ __forceinline__ void ldsm4(uint32_t* r, uint32_t addr) {
    asm volatile("ldmatrix.sync.aligned.m8n8.x4.shared.b16 {%0,%1,%2,%3}, [%4];"
                 : "=r"(r[0]), "=r"(r[1]), "=r"(r[2]), "=r"(r[3]) : "r"(addr));
}
__device__ __forceinline__ void mma_s8(int* c, const uint32_t* a,
                                       uint32_t b0, uint32_t b1) {
    asm volatile(
        "mma.sync.aligned.m16n8k32.row.col.s32.s8.s8.s32 "
        "{%0,%1,%2,%3}, {%4,%5,%6,%7}, {%8,%9}, {%0,%1,%2,%3};"
        : "+r"(c[0]), "+r"(c[1]), "+r"(c[2]), "+r"(c[3])
        : "r"(a[0]), "r"(a[1]), "r"(a[2]), "r"(a[3]), "r"(b0), "r"(b1));
}

// 128-byte K-chunk per stage, padded row stride 144 bytes
#define ROWB 144
#define TILEB (128 * ROWB)          // 18432 (128-row x 128B tile + pad)
#define TILEA64 (64 * ROWB)         // 9216
#define NSTAGE 3
#define KSTAGES 12                  // 1536 bytes / 128
#define PASS1 4                     // stages 0..3 -> acc0; 4..11 -> acc1
#define SMEM_G (NSTAGE * 2 * TILEB)            // 110592
#define FSTAGE (TILEA64 + 2 * TILEB)           // 46080
#define SMEM_F (NSTAGE * FSTAGE)               // 138240

// ===========================================================================
// Generic int8 GEMM (trunk + lc): 256 thr, 8 warps (2x4), 64x32 warp tiles.
// ===========================================================================
template <int EPI>
__global__ __launch_bounds__(256) void gemm_i8(
    const int8_t* __restrict__ qA, const float* __restrict__ sA,
    const int8_t* __restrict__ qB, const float* __restrict__ sB,
    float* __restrict__ C, int Nout,
    const float* __restrict__ bias, const float* __restrict__ gamma,
    const float* __restrict__ beta, const float* __restrict__ resid)
{
    extern __shared__ char dsm[];
    const uint32_t sb = smem_u32(dsm);

    const int tid = threadIdx.x;
    const int lane = tid & 31;
    const int wid = tid >> 5;
    const int warp_m = wid >> 2;
    const int warp_n = wid & 3;
    const int bm = blockIdx.y * 128;
    const int bn = blockIdx.x * 128;

    const int8_t* Asrc[3] = { qA + (size_t)bm * 1024,
                              qA + (size_t)bm * 1024,
                              qA + (size_t)bm * 1024 + 512 };
    const int8_t* Bsrc[3] = { qB + (size_t)bn * 1024,
                              qB + (size_t)bn * 1024 + 512,
                              qB + (size_t)bn * 1024 };

    const int arow = (lane & 7) + ((lane >> 3) & 1) * 8;
    const int asel = lane >> 4;
    const int brow = ((lane >> 4) & 1) * 8 + (lane & 7);
    const int bsel = (lane >> 3) & 1;
    const uint32_t a_lane = (uint32_t)(warp_m * 64 + arow) * ROWB;
    const uint32_t b_lane = (uint32_t)(warp_n * 32 + brow) * ROWB;

    int acc0[4][4][4], acc1[4][4][4];
#pragma unroll
    for (int i = 0; i < 4; i++)
#pragma unroll
        for (int j = 0; j < 4; j++)
#pragma unroll
            for (int u = 0; u < 4; u++) { acc0[i][j][u] = 0; acc1[i][j][u] = 0; }

    auto load_stage = [&](int s, int buf) {
        const int p = s >> 2;
        const int ko = (s & 3) * 128;
        const uint32_t ab = sb + buf * (2 * TILEB);
        const uint32_t bb = ab + TILEB;
        const int8_t* As = Asrc[p] + ko;
        const int8_t* Bs = Bsrc[p] + ko;
#pragma unroll
        for (int i = 0; i < 4; i++) {
            const int idx = tid + i * 256;
            const int r = idx >> 3, c = (idx & 7) * 16;
            CP16(ab + r * ROWB + c, As + (size_t)r * 1024 + c);
            CP16(bb + r * ROWB + c, Bs + (size_t)r * 1024 + c);
        }
    };

    load_stage(0, 0); CP_COMMIT();
    load_stage(1, 1); CP_COMMIT();

    int buf = 0;
    auto stage_body = [&](int s, int (&acc)[4][4][4]) {
        if (s + 2 < KSTAGES) { CP_WAIT1(); } else { CP_WAIT0(); }
        __syncthreads();
        if (s + 2 < KSTAGES) {
            int nb = buf + 2; if (nb >= NSTAGE) nb -= NSTAGE;
            load_stage(s + 2, nb);
            CP_COMMIT();
        }
        const uint32_t ab = sb + buf * (2 * TILEB);
        const uint32_t bb = ab + TILEB;
#pragma unroll
        for (int kh = 0; kh < 4; kh++) {
            uint32_t af[4][4], bf[2][4];
            const uint32_t kadd = kh * 32;
#pragma unroll
            for (int m = 0; m < 4; m++)
                ldsm4(af[m], ab + a_lane + m * (16 * ROWB) + kadd + asel * 16);
#pragma unroll
            for (int n2 = 0; n2 < 2; n2++)
                ldsm4(bf[n2], bb + b_lane + n2 * (16 * ROWB) + kadd + bsel * 16);
#pragma unroll
            for (int m = 0; m < 4; m++)
#pragma unroll
                for (int n = 0; n < 4; n++)
                    mma_s8(acc[m][n], af[m],
                           bf[n >> 1][(n & 1) * 2 + 0], bf[n >> 1][(n & 1) * 2 + 1]);
        }
        buf++; if (buf == NSTAGE) buf = 0;
    };

    for (int s = 0; s < PASS1; s++) stage_body(s, acc0);
    for (int s = PASS1; s < KSTAGES; s++) stage_body(s, acc1);

    // -------- epilogue --------
    const float RS = rsqrtf(1.0f + EPSV);
    const int lm = lane >> 2;
    const int ln2 = (lane & 3) * 2;
    const int row0 = bm + warp_m * 64;
    const int col0 = bn + warp_n * 32;

#pragma unroll
    for (int m = 0; m < 4; m++) {
        const int r_lo = row0 + m * 16 + lm;
        const int r_hi = r_lo + 8;
        const float sa0 = sA[r_lo], sa1 = sA[r_hi];
#pragma unroll
        for (int n = 0; n < 4; n++) {
            const int gn = col0 + n * 8 + ln2;
            if (EPI == 0 && gn >= Nout) continue;
            const float sb0 = sB[gn], sb1 = sB[gn + 1];
            const int* c0 = acc0[m][n];
            const int* c1 = acc1[m][n];
            float v[4];
            v[0] = ((float)c0[0] + (float)c1[0] * INV254) * (sa0 * sb0);
            v[1] = ((float)c0[1] + (float)c1[1] * INV254) * (sa0 * sb1);
            v[2] = ((float)c0[2] + (float)c1[2] * INV254) * (sa1 * sb0);
            v[3] = ((float)c0[3] + (float)c1[3] * INV254) * (sa1 * sb1);
            const float bz0 = bias[gn], bz1 = bias[gn + 1];
            if (EPI == 0) {
                *(float2*)(C + (size_t)r_lo * Nout + gn) = make_float2(v[0] + bz0, v[1] + bz1);
                *(float2*)(C + (size_t)r_hi * Nout + gn) = make_float2(v[2] + bz0, v[3] + bz1);
            } else {
                const float s0 = gamma[gn] * RS, s1 = gamma[gn + 1] * RS;
                const float e0 = beta[gn], e1 = beta[gn + 1];
                v[0] = (v[0] + bz0) * s0 + e0; v[1] = (v[1] + bz1) * s1 + e1;
                v[2] = (v[2] + bz0) * s0 + e0; v[3] = (v[3] + bz1) * s1 + e1;
#pragma unroll
                for (int u = 0; u < 4; u++) {
                    if (EPI == 1) v[u] = fmaxf(v[u], 0.0f);
                    else v[u] = 0.5f * v[u] * (1.0f + erff(v[u] * 0.70710678118654752f));
                }
                if (EPI == 3) {
                    const float2 r0 = *(const float2*)(resid + (size_t)r_lo * HH + gn);
                    const float2 r1 = *(const float2*)(resid + (size_t)r_hi * HH + gn);
                    v[0] += r0.x; v[1] += r0.y; v[2] += r1.x; v[3] += r1.y;
                }
                *(float2*)(C + (size_t)r_lo * HH + gn) = make_float2(v[0], v[1]);
                *(float2*)(C + (size_t)r_hi * HH + gn) = make_float2(v[2], v[3]);
            }
        }
    }
}

// ===========================================================================
// Fused int8 fi/fs head + node reduction. 64x128 CTA, 256 thr, 8 warps (2x4),
// 32x32 dual-function dual-plane warp tiles. grid (60, 128).
// ===========================================================================
__global__ __launch_bounds__(256, 1) void gemm_fifs_i8(
    const int8_t* __restrict__ qA, const float* __restrict__ sA,
    const int8_t* __restrict__ qBi, const float* __restrict__ sBi,
    const int8_t* __restrict__ qBs, const float* __restrict__ sBs,
    const float* __restrict__ x,
    const float* __restrict__ b_fi, const float* __restrict__ b_fs,
    float* __restrict__ pse, float* __restrict__ psx, float* __restrict__ psf)
{
    extern __shared__ char dsm[];
    const uint32_t sb = smem_u32(dsm);

    const int tid = threadIdx.x;
    const int lane = tid & 31;
    const int wid = tid >> 5;
    const int warp_m = wid >> 2;
    const int warp_n = wid & 3;
    const int ct = blockIdx.x;
    const int bm = blockIdx.y * 64;
    const int bn = ct * 128;
    const int node = ct >> 2;
    const int slice = (ct & 3) * 4 + warp_n;
    const int xbase = (ct & 3) * 128 + warp_n * 32;

    const int8_t* Asrc[3] = { qA + (size_t)bm * 1024,
                              qA + (size_t)bm * 1024,
                              qA + (size_t)bm * 1024 + 512 };
    const int8_t* BiP[3] = { qBi + (size_t)bn * 1024,
                             qBi + (size_t)bn * 1024 + 512,
                             qBi + (size_t)bn * 1024 };
    const int8_t* BsP[3] = { qBs + (size_t)bn * 1024,
                             qBs + (size_t)bn * 1024 + 512,
                             qBs + (size_t)bn * 1024 };

    const int arow = (lane & 7) + ((lane >> 3) & 1) * 8;
    const int asel = lane >> 4;
    const int brow = ((lane >> 4) & 1) * 8 + (lane & 7);
    const int bsel = (lane >> 3) & 1;
    const uint32_t a_lane = (uint32_t)(warp_m * 32 + arow) * ROWB;
    const uint32_t b_lane = (uint32_t)(warp_n * 32 + brow) * ROWB;

    int aI0[2][4][4], aI1[2][4][4], aS0[2][4][4], aS1[2][4][4];
#pragma unroll
    for (int i = 0; i < 2; i++)
#pragma unroll
        for (int j = 0; j < 4; j++)
#pragma unroll
            for (int u = 0; u < 4; u++) {
                aI0[i][j][u] = 0; aI1[i][j][u] = 0;
                aS0[i][j][u] = 0; aS1[i][j][u] = 0;
            }

    auto load_stage = [&](int s, int buf) {
        const int p = s >> 2;
        const int ko = (s & 3) * 128;
        const uint32_t ab = sb + buf * FSTAGE;
        const uint32_t ib = ab + TILEA64;
        const uint32_t qb = ib + TILEB;
#pragma unroll
        for (int i = 0; i < 2; i++) {  // A: 64 rows x 128B = 512 chunks
            const int idx = tid + i * 256;
            const int r = idx >> 3, c = (idx & 7) * 16;
            CP16(ab + r * ROWB + c, Asrc[p] + ko + (size_t)r * 1024 + c);
        }
#pragma unroll
        for (int i = 0; i < 4; i++) {  // B tiles: 1024 chunks each
            const int idx = tid + i * 256;
            const int r = idx >> 3, c = (idx & 7) * 16;
            CP16(ib + r * ROWB + c, BiP[p] + ko + (size_t)r * 1024 + c);
            CP16(qb + r * ROWB + c, BsP[p] + ko + (size_t)r * 1024 + c);
        }
    };

    load_stage(0, 0); CP_COMMIT();
    load_stage(1, 1); CP_COMMIT();

    int buf = 0;
    auto stage_body = [&](int s, int (&aI)[2][4][4], int (&aS)[2][4][4]) {
        if (s + 2 < KSTAGES) { CP_WAIT1(); } else { CP_WAIT0(); }
        __syncthreads();
        if (s + 2 < KSTAGES) {
            int nb = buf + 2; if (nb >= NSTAGE) nb -= NSTAGE;
            load_stage(s + 2, nb);
            CP_COMMIT();
        }
        const uint32_t ab = sb + buf * FSTAGE;
        const uint32_t ib = ab + TILEA64;
        const uint32_t qb = ib + TILEB;
#pragma unroll
        for (int kh = 0; kh < 4; kh++) {
            uint32_t af[2][4], bi[2][4], bq[2][4];
            const uint32_t kadd = kh * 32;
#pragma unroll
            for (int m = 0; m < 2; m++)
                ldsm4(af[m], ab + a_lane + m * (16 * ROWB) + kadd + asel * 16);
#pragma unroll
            for (int n2 = 0; n2 < 2; n2++) {
                ldsm4(bi[n2], ib + b_lane + n2 * (16 * ROWB) + kadd + bsel * 16);
                ldsm4(bq[n2], qb + b_lane + n2 * (16 * ROWB) + kadd + bsel * 16);
            }
#pragma unroll
            for (int m = 0; m < 2; m++)
#pragma unroll
                for (int n = 0; n < 4; n++) {
                    mma_s8(aI[m][n], af[m],
                           bi[n >> 1][(n & 1) * 2 + 0], bi[n >> 1][(n & 1) * 2 + 1]);
                    mma_s8(aS[m][n], af[m],
                           bq[n >> 1][(n & 1) * 2 + 0], bq[n >> 1][(n & 1) * 2 + 1]);
                }
        }
        buf++; if (buf == NSTAGE) buf = 0;
    };

    for (int s = 0; s < PASS1; s++) stage_body(s, aI0, aS0);
    for (int s = PASS1; s < KSTAGES; s++) stage_body(s, aI1, aS1);

    // -------- fused reduction epilogue --------
    const int lm = lane >> 2;
    const int ln2 = (lane & 3) * 2;
    const int row0 = bm + warp_m * 32;
    const int col0 = bn + warp_n * 32;

    float sa[2][2];
#pragma unroll
    for (int m = 0; m < 2; m++) {
        sa[m][0] = sA[row0 + m * 16 + lm];
        sa[m][1] = sA[row0 + m * 16 + lm + 8];
    }

    float se[4], sx[4], sf[4];
#pragma unroll
    for (int i = 0; i < 4; i++) { se[i] = 0.f; sx[i] = 0.f; sf[i] = 0.f; }

#pragma unroll
    for (int n = 0; n < 4; n++) {
        const int gn = col0 + n * 8 + ln2;
        const int xc = xbase + n * 8 + ln2;
        const float bi0 = b_fi[gn], bi1 = b_fi[gn + 1];
        const float bs0 = b_fs[gn], bs1 = b_fs[gn + 1];
        const float si0 = sBi[gn], si1 = sBi[gn + 1];
        const float ss0 = sBs[gn], ss1 = sBs[gn + 1];
#pragma unroll
        for (int m = 0; m < 2; m++) {
            const int r_lo = row0 + m * 16 + lm;
            const int r_hi = r_lo + 8;
            const int* i0 = aI0[m][n]; const int* i1 = aI1[m][n];
            const int* s0 = aS0[m][n]; const int* s1 = aS1[m][n];
            const float fi0 = ((float)i0[0] + (float)i1[0] * INV254) * (sa[m][0] * si0) + bi0;
            const float fi1 = ((float)i0[1] + (float)i1[1] * INV254) * (sa[m][0] * si1) + bi1;
            const float fi2 = ((float)i0[2] + (float)i1[2] * INV254) * (sa[m][1] * si0) + bi0;
            const float fi3 = ((float)i0[3] + (float)i1[3] * INV254) * (sa[m][1] * si1) + bi1;
            const float fs0 = ((float)s0[0] + (float)s1[0] * INV254) * (sa[m][0] * ss0) + bs0;
            const float fs1 = ((float)s0[1] + (float)s1[1] * INV254) * (sa[m][0] * ss1) + bs1;
            const float fs2 = ((float)s0[2] + (float)s1[2] * INV254) * (sa[m][1] * ss0) + bs0;
            const float fs3 = ((float)s0[3] + (float)s1[3] * INV254) * (sa[m][1] * ss1) + bs1;
            const float e0 = __expf(fi0);
            const float e1 = __expf(fi1);
            const float e2 = __expf(fi2);
            const float e3 = __expf(fi3);
            const float2 x0 = *(const float2*)(x + (size_t)r_lo * FF + xc);
            const float2 x1 = *(const float2*)(x + (size_t)r_hi * FF + xc);
            se[m * 2 + 0] += e0 + e1;
            se[m * 2 + 1] += e2 + e3;
            sx[m * 2 + 0] += e0 * x0.x + e1 * x0.y;
            sx[m * 2 + 1] += e2 * x1.x + e3 * x1.y;
            sf[m * 2 + 0] += e0 * fs0 + e1 * fs1;
            sf[m * 2 + 1] += e2 * fs2 + e3 * fs3;
        }
    }

#pragma unroll
    for (int i = 0; i < 4; i++) {
        se[i] += __shfl_xor_sync(0xffffffffu, se[i], 1);
        se[i] += __shfl_xor_sync(0xffffffffu, se[i], 2);
        sx[i] += __shfl_xor_sync(0xffffffffu, sx[i], 1);
        sx[i] += __shfl_xor_sync(0xffffffffu, sx[i], 2);
        sf[i] += __shfl_xor_sync(0xffffffffu, sf[i], 1);
        sf[i] += __shfl_xor_sync(0xffffffffu, sf[i], 2);
    }
    if ((lane & 3) == 0) {
#pragma unroll
        for (int i = 0; i < 4; i++) {
            const int row = row0 + (i >> 1) * 16 + lm + (i & 1) * 8;
            const size_t o = ((size_t)row * NNODES + node) * 16 + slice;
            pse[o] = se[i]; psx[o] = sx[i]; psf[o] = sf[i];
        }
    }
}

// ---------------- per-row two-plane int8 quantization of activations --------
__global__ __launch_bounds__(256) void quant_act(
    const float* __restrict__ src, int8_t* __restrict__ q, float* __restrict__ s)
{
    const int row = blockIdx.x * 8 + (threadIdx.x >> 5);
    const int lane = threadIdx.x & 31;
    const float4* rp = (const float4*)(src + (size_t)row * 512);

    float4 v[4];
    float m = 0.0f;
#pragma unroll
    for (int i = 0; i < 4; i++) {
        v[i] = rp[i * 32 + lane];
        m = fmaxf(m, fmaxf(fmaxf(fabsf(v[i].x), fabsf(v[i].y)),
                           fmaxf(fabsf(v[i].z), fabsf(v[i].w))));
    }
#pragma unroll
    for (int o = 16; o > 0; o >>= 1)
        m = fmaxf(m, __shfl_xor_sync(0xffffffffu, m, o));

    const float inv = (m > 0.0f) ? 127.0f / m : 0.0f;
    if (lane == 0) s[row] = m * (1.0f / 127.0f);

    int8_t* q1p = q + (size_t)row * 1024;
    int8_t* q2p = q1p + 512;
#pragma unroll
    for (int i = 0; i < 4; i++) {
        const float* f = &v[i].x;
        char4 c1, c2;
        signed char* p1 = &c1.x;
        signed char* p2 = &c2.x;
#pragma unroll
        for (int u = 0; u < 4; u++) {
            const float t = f[u] * inv;
            const float a = rintf(t);
            const float b = rintf((t - a) * 254.0f);
            p1[u] = (signed char)(int)a;
            p2[u] = (signed char)(int)b;
        }
        ((char4*)q1p)[i * 32 + lane] = c1;
        ((char4*)q2p)[i * 32 + lane] = c2;
    }
}

// ---------------- transpose + per-column two-plane int8 weight quant --------
__global__ __launch_bounds__(256) void quant_w(
    const float* __restrict__ W, int8_t* __restrict__ q, float* __restrict__ s, int N)
{
    __shared__ float wm[8][32];
    __shared__ float invs[32];
    __shared__ int8_t qs[32][1040];

    const int n0 = blockIdx.x * 32;
    const int tx = threadIdx.x & 31;
    const int wy = threadIdx.x >> 5;
    const int n = n0 + tx;
    const bool ok = n < N;

    float m = 0.0f;
    for (int k = wy; k < 512; k += 8) {
        const float v = ok ? W[(size_t)k * N + n] : 0.0f;
        m = fmaxf(m, fabsf(v));
    }
    wm[wy][tx] = m;
    __syncthreads();
    if (threadIdx.x < 32) {
        float mm = wm[0][threadIdx.x];
#pragma unroll
        for (int w = 1; w < 8; w++) mm = fmaxf(mm, wm[w][threadIdx.x]);
        invs[threadIdx.x] = (mm > 0.0f) ? 127.0f / mm : 0.0f;
        s[n0 + threadIdx.x] = mm * (1.0f / 127.0f);
    }
    __syncthreads();

    const float inv = invs[tx];
    for (int k = wy; k < 512; k += 8) {
        const float v = ok ? W[(size_t)k * N + n] : 0.0f;
        const float t = v * inv;
        const float a = rintf(t);
        const float b = rintf((t - a) * 254.0f);
        qs[tx][k] = (int8_t)(int)a;
        qs[tx][512 + k] = (int8_t)(int)b;
    }
    __syncthreads();

#pragma unroll
    for (int i = 0; i < 8; i++) {
        const int idx = threadIdx.x + i * 256;
        const int row = idx >> 6;
        const int c = (idx & 63) * 16;
        *(uint4*)(q + (size_t)(n0 + row) * 1024 + c) = *(uint4*)(&qs[row][c]);
    }
}

// ---------------- sd + tree combine -----------------------------------------
__global__ __launch_bounds__(128) void sd_combine_kernel(
    const float* __restrict__ pse, const float* __restrict__ psx,
    const float* __restrict__ psf, const float* __restrict__ lnc,
    float* __restrict__ out)
{
    __shared__ float s_sd[NNODES];
    __shared__ float coeff[NLEAVES];
    const int b = blockIdx.x;
    const int tid = threadIdx.x;

    if (tid < NNODES) {
        const size_t base = ((size_t)b * NNODES + tid) * 16;
        float se = 0.f, sx = 0.f, sf = 0.f;
#pragma unroll
        for (int q = 0; q < 16; q++) {
            se += pse[base + q]; sx += psx[base + q]; sf += psf[base + q];
        }
        const float z = (sx - sf) / se;
        s_sd[tid] = 1.0f / (1.0f + expf(-z));
    }
    __syncthreads();
    if (tid < NLEAVES) {
        const int l = tid;
        float p, c;
        p = s_sd[0];            c  = ((l >> 3) & 1) ? 1.0f - p : p;
        p = s_sd[1 + (l >> 3)]; c *= ((l >> 2) & 1) ? 1.0f - p : p;
        p = s_sd[3 + (l >> 2)]; c *= ((l >> 1) & 1) ? 1.0f - p : p;
        p = s_sd[7 + (l >> 1)]; c *= (l & 1)        ? 1.0f - p : p;
        coeff[l] = c;
    }
    __syncthreads();
    if (tid < CC) {
        const float* lp = lnc + (size_t)b * (NLEAVES * CC) + tid;
        float acc = 0.0f;
#pragma unroll
        for (int l = 0; l < NLEAVES; l++) acc += coeff[l] * lp[l * CC];
        out[b * CC + tid] = acc;
    }
}

// ===========================================================================
extern "C" void kernel_launch(void* const* d_in, const int* in_sizes, int n_in,
                              void* d_out, int out_size)
{
    const float* x    = (const float*)d_in[0];
    const float* w_in = (const float*)d_in[1];
    const float* b_in = (const float*)d_in[2];
    const float* g0   = (const float*)d_in[3];
    const float* be0  = (const float*)d_in[4];
    const float* bw1  = (const float*)d_in[5];
    const float* bb1  = (const float*)d_in[6];
    const float* bg1  = (const float*)d_in[7];
    const float* bbe1 = (const float*)d_in[8];
    const float* bw2  = (const float*)d_in[9];
    const float* bb2  = (const float*)d_in[10];
    const float* bg2  = (const float*)d_in[11];
    const float* bbe2 = (const float*)d_in[12];
    const float* w_fi = (const float*)d_in[13];
    const float* b_fi = (const float*)d_in[14];
    const float* w_fs = (const float*)d_in[15];
    const float* b_fs = (const float*)d_in[16];
    const float* w_lc = (const float*)d_in[17];
    const float* b_lc = (const float*)d_in[18];
    float* out = (float*)d_out;

    int8_t *qact, *qwi, *qw1, *qw2, *qwfi, *qwfs, *qwlc;
    float *sact, *swi, *sw1, *sw2, *swfi, *swfs, *swlc;
    float *h0, *h1, *ht, *lc, *pse, *psx, *psf;
    cudaGetSymbolAddress((void**)&qact, g_qact); cudaGetSymbolAddress((void**)&sact, g_sact);
    cudaGetSymbolAddress((void**)&qwi, g_qwi);   cudaGetSymbolAddress((void**)&swi, g_swi);
    cudaGetSymbolAddress((void**)&qw1, g_qw1);   cudaGetSymbolAddress((void**)&sw1, g_sw1);
    cudaGetSymbolAddress((void**)&qw2, g_qw2);   cudaGetSymbolAddress((void**)&sw2, g_sw2);
    cudaGetSymbolAddress((void**)&qwfi, g_qwfi); cudaGetSymbolAddress((void**)&swfi, g_swfi);
    cudaGetSymbolAddress((void**)&qwfs, g_qwfs); cudaGetSymbolAddress((void**)&swfs, g_swfs);
    cudaGetSymbolAddress((void**)&qwlc, g_qwlc); cudaGetSymbolAddress((void**)&swlc, g_swlc);
    cudaGetSymbolAddress((void**)&h0, g_h0);     cudaGetSymbolAddress((void**)&h1, g_h1);
    cudaGetSymbolAddress((void**)&ht, g_ht);     cudaGetSymbolAddress((void**)&lc, g_lc);
    cudaGetSymbolAddress((void**)&pse, g_pse);
    cudaGetSymbolAddress((void**)&psx, g_psx);
    cudaGetSymbolAddress((void**)&psf, g_psf);

    cudaFuncSetAttribute(gemm_i8<0>, cudaFuncAttributeMaxDynamicSharedMemorySize, SMEM_G);
    cudaFuncSetAttribute(gemm_i8<1>, cudaFuncAttributeMaxDynamicSharedMemorySize, SMEM_G);
    cudaFuncSetAttribute(gemm_i8<2>, cudaFuncAttributeMaxDynamicSharedMemorySize, SMEM_G);
    cudaFuncSetAttribute(gemm_i8<3>, cudaFuncAttributeMaxDynamicSharedMemorySize, SMEM_G);
    cudaFuncSetAttribute(gemm_fifs_i8, cudaFuncAttributeMaxDynamicSharedMemorySize, SMEM_F);

    const dim3 g512(HH / 128, BQ / 128);
    const dim3 gfi(NFI / 128, BQ / 64);
    const dim3 glc(NLCP / 128, BQ / 128);
    const int QAB = BQ / 8;

    // ---- side stream: weight quant + lc GEMM (overlaps the main chain) ----
    cudaStream_t s2;
    cudaStreamCreateWithFlags(&s2, cudaStreamNonBlocking);
    cudaEvent_t evFork, evA, evB, evC, evD, evE, evF, evG, evH;
    cudaEventCreateWithFlags(&evFork, cudaEventDisableTiming);
    cudaEventCreateWithFlags(&evA, cudaEventDisableTiming);
    cudaEventCreateWithFlags(&evB, cudaEventDisableTiming);
    cudaEventCreateWithFlags(&evC, cudaEventDisableTiming);
    cudaEventCreateWithFlags(&evD, cudaEventDisableTiming);
    cudaEventCreateWithFlags(&evE, cudaEventDisableTiming);
    cudaEventCreateWithFlags(&evF, cudaEventDisableTiming);
    cudaEventCreateWithFlags(&evG, cudaEventDisableTiming);
    cudaEventCreateWithFlags(&evH, cudaEventDisableTiming);

    cudaEventRecord(evFork, 0);
    cudaStreamWaitEvent(s2, evFork, 0);

    quant_act<<<QAB, 256>>>(x, qact, sact);
    quant_w<<<HH / 32, 256, 0, s2>>>(w_in, qwi, swi, HH);
    cudaEventRecord(evA, s2);
    quant_w<<<HH / 32, 256, 0, s2>>>(bw1, qw1, sw1, HH);
    cudaEventRecord(evB, s2);
    cudaStreamWaitEvent(0, evA, 0);
    gemm_i8<1><<<g512, 256, SMEM_G>>>(qact, sact, qwi, swi,
        h0, HH, b_in, g0, be0, nullptr);
    quant_act<<<QAB, 256>>>(h0, qact, sact);
    quant_w<<<HH / 32, 256, 0, s2>>>(bw2, qw2, sw2, HH);
    cudaEventRecord(evC, s2);
    quant_w<<<HH / 32, 256, 0, s2>>>(bw1 + HH * HH, qw1 + (size_t)HH * 1024, sw1 + HH, HH);
    cudaEventRecord(evD, s2);
    quant_w<<<HH / 32, 256, 0, s2>>>(bw2 + HH * HH, qw2 + (size_t)HH * 1024, sw2 + HH, HH);
    cudaEventRecord(evE, s2);
    quant_w<<<NFI / 32, 256, 0, s2>>>(w_fi, qwfi, swfi, NFI);
    quant_w<<<NFI / 32, 256, 0, s2>>>(w_fs, qwfs, swfs, NFI);
    quant_w<<<NLCP / 32, 256, 0, s2>>>(w_lc, qwlc, swlc, NLC);
    cudaEventRecord(evF, s2);

    cudaStreamWaitEvent(0, evB, 0);
    gemm_i8<2><<<g512, 256, SMEM_G>>>(qact, sact, qw1, sw1,
        ht, HH, bb1, bg1, bbe1, nullptr);
    quant_act<<<QAB, 256>>>(ht, qact, sact);
    cudaStreamWaitEvent(0, evC, 0);
    gemm_i8<3><<<g512, 256, SMEM_G>>>(qact, sact, qw2, sw2,
        h1, HH, bb2, bg2, bbe2, h0);
    quant_act<<<QAB, 256>>>(h1, qact, sact);
    cudaStreamWaitEvent(0, evD, 0);
    gemm_i8<2><<<g512, 256, SMEM_G>>>(qact, sact, qw1 + (size_t)HH * 1024, sw1 + HH,
        ht, HH, bb1 + HH, bg1 + HH, bbe1 + HH, nullptr);
    quant_act<<<QAB, 256>>>(ht, qact, sact);
    cudaStreamWaitEvent(0, evE, 0);
    gemm_i8<3><<<g512, 256, SMEM_G>>>(qact, sact, qw2 + (size_t)HH * 1024, sw2 + HH,
        h0, HH, bb2 + HH, bg2 + HH, bbe2 + HH, h1);
    cudaStreamWaitEvent(0, evF, 0);
    quant_act<<<QAB, 256>>>(h0, qact, sact);
    cudaEventRecord(evG, 0);

    // lc GEMM on side stream, concurrent with fifs
    cudaStreamWaitEvent(s2, evG, 0);
    gemm_i8<0><<<glc, 256, SMEM_G, s2>>>(qact, sact, qwlc, swlc,
        lc, NLC, b_lc, nullptr, nullptr, nullptr);
    cudaEventRecord(evH, s2);

    gemm_fifs_i8<<<gfi, 256, SMEM_F>>>(qact, sact, qwfi, swfi, qwfs, swfs,
                                       x, b_fi, b_fs, pse, psx, psf);
    cudaStreamWaitEvent(0, evH, 0);
    sd_combine_kernel<<<BQ, 128>>>(pse, psx, psf, lc, out);
}

// round 13
// speedup vs baseline: 1.1561x; 1.0078x over previous
#include <cuda_runtime.h>
#include <cstdint>
#include <math.h>

// ===========================================================================
// DTHyperNet via int8 IMMA digit-planes (mma.sync.m16n8k32.s8, s32 accum)
//   v = (rowmax/127) * (q1 + q2/254);  D = sA*sB*(P11 + (P12+P21)/254)
// 12-stage 128B-chunk pipeline; fifs processes 2 row-blocks per resident CTA
// (26 waves instead of 52); weight quant + lc GEMM overlapped on side stream.
// ===========================================================================

#define BQ 8192
#define FF 512
#define HH 512
#define CC 100
#define NNODES 15
#define NLEAVES 16
#define NFI 7680
#define NLC 1600
#define NLCP 1664
#define EPSV 1e-5f
#define INV254 (1.0f / 254.0f)

// -------------------- device scratch (no allocations allowed) --------------
__device__ int8_t g_qact[(size_t)BQ * 1024];
__device__ float  g_sact[BQ];
__device__ float  g_h0[(size_t)BQ * HH];
__device__ float  g_h1[(size_t)BQ * HH];
__device__ float  g_ht[(size_t)BQ * HH];
__device__ int8_t g_qwi[(size_t)HH * 1024];
__device__ int8_t g_qw1[(size_t)2 * HH * 1024];
__device__ int8_t g_qw2[(size_t)2 * HH * 1024];
__device__ int8_t g_qwfi[(size_t)NFI * 1024];
__device__ int8_t g_qwfs[(size_t)NFI * 1024];
__device__ int8_t g_qwlc[(size_t)NLCP * 1024];
__device__ float  g_swi[HH], g_sw1[2 * HH], g_sw2[2 * HH];
__device__ float  g_swfi[NFI], g_swfs[NFI], g_swlc[NLCP];
__device__ float  g_lc[(size_t)BQ * NLC];
__device__ float  g_pse[(size_t)BQ * NNODES * 16];
__device__ float  g_psx[(size_t)BQ * NNODES * 16];
__device__ float  g_psf[(size_t)BQ * NNODES * 16];

// -------------------- PTX helpers (sm_80 baseline only) --------------------
__device__ __forceinline__ uint32_t smem_u32(const void* p) {
    uint32_t a;
    asm("{ .reg .u64 t; cvta.to.shared.u64 t, %1; cvt.u32.u64 %0, t; }"
        : "=r"(a) : "l"(p));
    return a;
}
#define CP16(dst, src) \
    asm volatile("cp.async.cg.shared.global [%0], [%1], 16;" :: "r"(dst), "l"(src))
#define CP_COMMIT() asm volatile("cp.async.commit_group;" ::: "memory")
#define CP_WAIT0() asm volatile("cp.async.wait_group 0;" ::: "memory")
#define CP_WAIT1() asm volatile("cp.async.wait_group 1;" ::: "memory")

__device__ __forceinline__ void ldsm4(uint32_t* r, uint32_t addr) {
    asm volatile("ldmatrix.sync.aligned.m8n8.x4.shared.b16 {%0,%1,%2,%3}, [%4];"
                 : "=r"(r[0]), "=r"(r[1]), "=r"(r[2]), "=r"(r[3]) : "r"(addr));
}
__device__ __forceinline__ void mma_s8(int* c, const uint32_t* a,
                                       uint32_t b0, uint32_t b1) {
    asm volatile(
        "mma.sync.aligned.m16n8k32.row.col.s32.s8.s8.s32 "
        "{%0,%1,%2,%3}, {%4,%5,%6,%7}, {%8,%9}, {%0,%1,%2,%3};"
        : "+r"(c[0]), "+r"(c[1]), "+r"(c[2]), "+r"(c[3])
        : "r"(a[0]), "r"(a[1]), "r"(a[2]), "r"(a[3]), "r"(b0), "r"(b1));
}

// 128-byte K-chunk per stage, padded row stride 144 bytes
#define ROWB 144
#define TILEB (128 * ROWB)          // 18432
#define TILEA64 (64 * ROWB)         // 9216
#define NSTAGE 3
#define KSTAGES 12                  // 1536 bytes / 128
#define PASS1 4
#define SMEM_G (NSTAGE * 2 * TILEB)            // 110592
#define FSTAGE (TILEA64 + 2 * TILEB)           // 46080
#define SMEM_F (NSTAGE * FSTAGE)               // 138240

// ===========================================================================
// Generic int8 GEMM (trunk + lc): 256 thr, 8 warps (2x4), 64x32 warp tiles.
// ===========================================================================
template <int EPI>
__global__ __launch_bounds__(256) void gemm_i8(
    const int8_t* __restrict__ qA, const float* __restrict__ sA,
    const int8_t* __restrict__ qB, const float* __restrict__ sB,
    float* __restrict__ C, int Nout,
    const float* __restrict__ bias, const float* __restrict__ gamma,
    const float* __restrict__ beta, const float* __restrict__ resid)
{
    extern __shared__ char dsm[];
    const uint32_t sb = smem_u32(dsm);

    const int tid = threadIdx.x;
    const int lane = tid & 31;
    const int wid = tid >> 5;
    const int warp_m = wid >> 2;
    const int warp_n = wid & 3;
    const int bm = blockIdx.y * 128;
    const int bn = blockIdx.x * 128;

    const int8_t* Asrc[3] = { qA + (size_t)bm * 1024,
                              qA + (size_t)bm * 1024,
                              qA + (size_t)bm * 1024 + 512 };
    const int8_t* Bsrc[3] = { qB + (size_t)bn * 1024,
                              qB + (size_t)bn * 1024 + 512,
                              qB + (size_t)bn * 1024 };

    const int arow = (lane & 7) + ((lane >> 3) & 1) * 8;
    const int asel = lane >> 4;
    const int brow = ((lane >> 4) & 1) * 8 + (lane & 7);
    const int bsel = (lane >> 3) & 1;
    const uint32_t a_lane = (uint32_t)(warp_m * 64 + arow) * ROWB;
    const uint32_t b_lane = (uint32_t)(warp_n * 32 + brow) * ROWB;

    int acc0[4][4][4], acc1[4][4][4];
#pragma unroll
    for (int i = 0; i < 4; i++)
#pragma unroll
        for (int j = 0; j < 4; j++)
#pragma unroll
            for (int u = 0; u < 4; u++) { acc0[i][j][u] = 0; acc1[i][j][u] = 0; }

    auto load_stage = [&](int s, int buf) {
        const int p = s >> 2;
        const int ko = (s & 3) * 128;
        const uint32_t ab = sb + buf * (2 * TILEB);
        const uint32_t bb = ab + TILEB;
        const int8_t* As = Asrc[p] + ko;
        const int8_t* Bs = Bsrc[p] + ko;
#pragma unroll
        for (int i = 0; i < 4; i++) {
            const int idx = tid + i * 256;
            const int r = idx >> 3, c = (idx & 7) * 16;
            CP16(ab + r * ROWB + c, As + (size_t)r * 1024 + c);
            CP16(bb + r * ROWB + c, Bs + (size_t)r * 1024 + c);
        }
    };

    load_stage(0, 0); CP_COMMIT();
    load_stage(1, 1); CP_COMMIT();

    int buf = 0;
    auto stage_body = [&](int s, int (&acc)[4][4][4]) {
        if (s + 2 < KSTAGES) { CP_WAIT1(); } else { CP_WAIT0(); }
        __syncthreads();
        if (s + 2 < KSTAGES) {
            int nb = buf + 2; if (nb >= NSTAGE) nb -= NSTAGE;
            load_stage(s + 2, nb);
            CP_COMMIT();
        }
        const uint32_t ab = sb + buf * (2 * TILEB);
        const uint32_t bb = ab + TILEB;
#pragma unroll
        for (int kh = 0; kh < 4; kh++) {
            uint32_t af[4][4], bf[2][4];
            const uint32_t kadd = kh * 32;
#pragma unroll
            for (int m = 0; m < 4; m++)
                ldsm4(af[m], ab + a_lane + m * (16 * ROWB) + kadd + asel * 16);
#pragma unroll
            for (int n2 = 0; n2 < 2; n2++)
                ldsm4(bf[n2], bb + b_lane + n2 * (16 * ROWB) + kadd + bsel * 16);
#pragma unroll
            for (int m = 0; m < 4; m++)
#pragma unroll
                for (int n = 0; n < 4; n++)
                    mma_s8(acc[m][n], af[m],
                           bf[n >> 1][(n & 1) * 2 + 0], bf[n >> 1][(n & 1) * 2 + 1]);
        }
        buf++; if (buf == NSTAGE) buf = 0;
    };

    for (int s = 0; s < PASS1; s++) stage_body(s, acc0);
    for (int s = PASS1; s < KSTAGES; s++) stage_body(s, acc1);

    // -------- epilogue --------
    const float RS = rsqrtf(1.0f + EPSV);
    const int lm = lane >> 2;
    const int ln2 = (lane & 3) * 2;
    const int row0 = bm + warp_m * 64;
    const int col0 = bn + warp_n * 32;

#pragma unroll
    for (int m = 0; m < 4; m++) {
        const int r_lo = row0 + m * 16 + lm;
        const int r_hi = r_lo + 8;
        const float sa0 = sA[r_lo], sa1 = sA[r_hi];
#pragma unroll
        for (int n = 0; n < 4; n++) {
            const int gn = col0 + n * 8 + ln2;
            if (EPI == 0 && gn >= Nout) continue;
            const float sb0 = sB[gn], sb1 = sB[gn + 1];
            const int* c0 = acc0[m][n];
            const int* c1 = acc1[m][n];
            float v[4];
            v[0] = ((float)c0[0] + (float)c1[0] * INV254) * (sa0 * sb0);
            v[1] = ((float)c0[1] + (float)c1[1] * INV254) * (sa0 * sb1);
            v[2] = ((float)c0[2] + (float)c1[2] * INV254) * (sa1 * sb0);
            v[3] = ((float)c0[3] + (float)c1[3] * INV254) * (sa1 * sb1);
            const float bz0 = bias[gn], bz1 = bias[gn + 1];
            if (EPI == 0) {
                *(float2*)(C + (size_t)r_lo * Nout + gn) = make_float2(v[0] + bz0, v[1] + bz1);
                *(float2*)(C + (size_t)r_hi * Nout + gn) = make_float2(v[2] + bz0, v[3] + bz1);
            } else {
                const float s0 = gamma[gn] * RS, s1 = gamma[gn + 1] * RS;
                const float e0 = beta[gn], e1 = beta[gn + 1];
                v[0] = (v[0] + bz0) * s0 + e0; v[1] = (v[1] + bz1) * s1 + e1;
                v[2] = (v[2] + bz0) * s0 + e0; v[3] = (v[3] + bz1) * s1 + e1;
#pragma unroll
                for (int u = 0; u < 4; u++) {
                    if (EPI == 1) v[u] = fmaxf(v[u], 0.0f);
                    else v[u] = 0.5f * v[u] * (1.0f + erff(v[u] * 0.70710678118654752f));
                }
                if (EPI == 3) {
                    const float2 r0 = *(const float2*)(resid + (size_t)r_lo * HH + gn);
                    const float2 r1 = *(const float2*)(resid + (size_t)r_hi * HH + gn);
                    v[0] += r0.x; v[1] += r0.y; v[2] += r1.x; v[3] += r1.y;
                }
                *(float2*)(C + (size_t)r_lo * HH + gn) = make_float2(v[0], v[1]);
                *(float2*)(C + (size_t)r_hi * HH + gn) = make_float2(v[2], v[3]);
            }
        }
    }
}

// ===========================================================================
// Fused int8 fi/fs head + node reduction. 64x128 tile, 256 thr, 8 warps (2x4),
// 32x32 dual-function dual-plane warp tiles. grid (60, 64); each CTA loops
// over TWO 64-row blocks (stays resident -> half the wave transitions).
// ===========================================================================
__global__ __launch_bounds__(256, 1) void gemm_fifs_i8(
    const int8_t* __restrict__ qA, const float* __restrict__ sA,
    const int8_t* __restrict__ qBi, const float* __restrict__ sBi,
    const int8_t* __restrict__ qBs, const float* __restrict__ sBs,
    const float* __restrict__ x,
    const float* __restrict__ b_fi, const float* __restrict__ b_fs,
    float* __restrict__ pse, float* __restrict__ psx, float* __restrict__ psf)
{
    extern __shared__ char dsm[];
    const uint32_t sb = smem_u32(dsm);

    const int tid = threadIdx.x;
    const int lane = tid & 31;
    const int wid = tid >> 5;
    const int warp_m = wid >> 2;
    const int warp_n = wid & 3;
    const int ct = blockIdx.x;
    const int bn = ct * 128;
    const int node = ct >> 2;
    const int slice = (ct & 3) * 4 + warp_n;
    const int xbase = (ct & 3) * 128 + warp_n * 32;

    const int8_t* BiP[3] = { qBi + (size_t)bn * 1024,
                             qBi + (size_t)bn * 1024 + 512,
                             qBi + (size_t)bn * 1024 };
    const int8_t* BsP[3] = { qBs + (size_t)bn * 1024,
                             qBs + (size_t)bn * 1024 + 512,
                             qBs + (size_t)bn * 1024 };

    const int arow = (lane & 7) + ((lane >> 3) & 1) * 8;
    const int asel = lane >> 4;
    const int brow = ((lane >> 4) & 1) * 8 + (lane & 7);
    const int bsel = (lane >> 3) & 1;
    const uint32_t a_lane = (uint32_t)(warp_m * 32 + arow) * ROWB;
    const uint32_t b_lane = (uint32_t)(warp_n * 32 + brow) * ROWB;

    const int lm = lane >> 2;
    const int ln2 = (lane & 3) * 2;

    for (int rb = 0; rb < 2; rb++) {
        const int bm = (blockIdx.y * 2 + rb) * 64;
        const int8_t* Asrc[3] = { qA + (size_t)bm * 1024,
                                  qA + (size_t)bm * 1024,
                                  qA + (size_t)bm * 1024 + 512 };

        int aI0[2][4][4], aI1[2][4][4], aS0[2][4][4], aS1[2][4][4];
#pragma unroll
        for (int i = 0; i < 2; i++)
#pragma unroll
            for (int j = 0; j < 4; j++)
#pragma unroll
                for (int u = 0; u < 4; u++) {
                    aI0[i][j][u] = 0; aI1[i][j][u] = 0;
                    aS0[i][j][u] = 0; aS1[i][j][u] = 0;
                }

        auto load_stage = [&](int s, int buf) {
            const int p = s >> 2;
            const int ko = (s & 3) * 128;
            const uint32_t ab = sb + buf * FSTAGE;
            const uint32_t ib = ab + TILEA64;
            const uint32_t qb = ib + TILEB;
#pragma unroll
            for (int i = 0; i < 2; i++) {
                const int idx = tid + i * 256;
                const int r = idx >> 3, c = (idx & 7) * 16;
                CP16(ab + r * ROWB + c, Asrc[p] + ko + (size_t)r * 1024 + c);
            }
#pragma unroll
            for (int i = 0; i < 4; i++) {
                const int idx = tid + i * 256;
                const int r = idx >> 3, c = (idx & 7) * 16;
                CP16(ib + r * ROWB + c, BiP[p] + ko + (size_t)r * 1024 + c);
                CP16(qb + r * ROWB + c, BsP[p] + ko + (size_t)r * 1024 + c);
            }
        };

        load_stage(0, 0); CP_COMMIT();
        load_stage(1, 1); CP_COMMIT();

        int buf = 0;
        auto stage_body = [&](int s, int (&aI)[2][4][4], int (&aS)[2][4][4]) {
            if (s + 2 < KSTAGES) { CP_WAIT1(); } else { CP_WAIT0(); }
            __syncthreads();
            if (s + 2 < KSTAGES) {
                int nb = buf + 2; if (nb >= NSTAGE) nb -= NSTAGE;
                load_stage(s + 2, nb);
                CP_COMMIT();
            }
            const uint32_t ab = sb + buf * FSTAGE;
            const uint32_t ib = ab + TILEA64;
            const uint32_t qb = ib + TILEB;
#pragma unroll
            for (int kh = 0; kh < 4; kh++) {
                uint32_t af[2][4], bi[2][4], bq[2][4];
                const uint32_t kadd = kh * 32;
#pragma unroll
                for (int m = 0; m < 2; m++)
                    ldsm4(af[m], ab + a_lane + m * (16 * ROWB) + kadd + asel * 16);
#pragma unroll
                for (int n2 = 0; n2 < 2; n2++) {
                    ldsm4(bi[n2], ib + b_lane + n2 * (16 * ROWB) + kadd + bsel * 16);
                    ldsm4(bq[n2], qb + b_lane + n2 * (16 * ROWB) + kadd + bsel * 16);
                }
#pragma unroll
                for (int m = 0; m < 2; m++)
#pragma unroll
                    for (int n = 0; n < 4; n++) {
                        mma_s8(aI[m][n], af[m],
                               bi[n >> 1][(n & 1) * 2 + 0], bi[n >> 1][(n & 1) * 2 + 1]);
                        mma_s8(aS[m][n], af[m],
                               bq[n >> 1][(n & 1) * 2 + 0], bq[n >> 1][(n & 1) * 2 + 1]);
                    }
            }
            buf++; if (buf == NSTAGE) buf = 0;
        };

        for (int s = 0; s < PASS1; s++) stage_body(s, aI0, aS0);
        for (int s = PASS1; s < KSTAGES; s++) stage_body(s, aI1, aS1);

        // -------- fused reduction epilogue --------
        const int row0 = bm + warp_m * 32;
        const int col0 = bn + warp_n * 32;

        float sa[2][2];
#pragma unroll
        for (int m = 0; m < 2; m++) {
            sa[m][0] = sA[row0 + m * 16 + lm];
            sa[m][1] = sA[row0 + m * 16 + lm + 8];
        }

        float se[4], sx[4], sf[4];
#pragma unroll
        for (int i = 0; i < 4; i++) { se[i] = 0.f; sx[i] = 0.f; sf[i] = 0.f; }

#pragma unroll
        for (int n = 0; n < 4; n++) {
            const int gn = col0 + n * 8 + ln2;
            const int xc = xbase + n * 8 + ln2;
            const float bi0 = b_fi[gn], bi1 = b_fi[gn + 1];
            const float bs0 = b_fs[gn], bs1 = b_fs[gn + 1];
            const float si0 = sBi[gn], si1 = sBi[gn + 1];
            const float ss0 = sBs[gn], ss1 = sBs[gn + 1];
#pragma unroll
            for (int m = 0; m < 2; m++) {
                const int r_lo = row0 + m * 16 + lm;
                const int r_hi = r_lo + 8;
                const int* i0 = aI0[m][n]; const int* i1 = aI1[m][n];
                const int* s0 = aS0[m][n]; const int* s1 = aS1[m][n];
                const float fi0 = ((float)i0[0] + (float)i1[0] * INV254) * (sa[m][0] * si0) + bi0;
                const float fi1 = ((float)i0[1] + (float)i1[1] * INV254) * (sa[m][0] * si1) + bi1;
                const float fi2 = ((float)i0[2] + (float)i1[2] * INV254) * (sa[m][1] * si0) + bi0;
                const float fi3 = ((float)i0[3] + (float)i1[3] * INV254) * (sa[m][1] * si1) + bi1;
                const float fs0 = ((float)s0[0] + (float)s1[0] * INV254) * (sa[m][0] * ss0) + bs0;
                const float fs1 = ((float)s0[1] + (float)s1[1] * INV254) * (sa[m][0] * ss1) + bs1;
                const float fs2 = ((float)s0[2] + (float)s1[2] * INV254) * (sa[m][1] * ss0) + bs0;
                const float fs3 = ((float)s0[3] + (float)s1[3] * INV254) * (sa[m][1] * ss1) + bs1;
                const float e0 = __expf(fi0);
                const float e1 = __expf(fi1);
                const float e2 = __expf(fi2);
                const float e3 = __expf(fi3);
                const float2 x0 = *(const float2*)(x + (size_t)r_lo * FF + xc);
                const float2 x1 = *(const float2*)(x + (size_t)r_hi * FF + xc);
                se[m * 2 + 0] += e0 + e1;
                se[m * 2 + 1] += e2 + e3;
                sx[m * 2 + 0] += e0 * x0.x + e1 * x0.y;
                sx[m * 2 + 1] += e2 * x1.x + e3 * x1.y;
                sf[m * 2 + 0] += e0 * fs0 + e1 * fs1;
                sf[m * 2 + 1] += e2 * fs2 + e3 * fs3;
            }
        }

#pragma unroll
        for (int i = 0; i < 4; i++) {
            se[i] += __shfl_xor_sync(0xffffffffu, se[i], 1);
            se[i] += __shfl_xor_sync(0xffffffffu, se[i], 2);
            sx[i] += __shfl_xor_sync(0xffffffffu, sx[i], 1);
            sx[i] += __shfl_xor_sync(0xffffffffu, sx[i], 2);
            sf[i] += __shfl_xor_sync(0xffffffffu, sf[i], 1);
            sf[i] += __shfl_xor_sync(0xffffffffu, sf[i], 2);
        }
        if ((lane & 3) == 0) {
#pragma unroll
            for (int i = 0; i < 4; i++) {
                const int row = row0 + (i >> 1) * 16 + lm + (i & 1) * 8;
                const size_t o = ((size_t)row * NNODES + node) * 16 + slice;
                pse[o] = se[i]; psx[o] = sx[i]; psf[o] = sf[i];
            }
        }
    }
}

// ---------------- per-row two-plane int8 quantization of activations --------
__global__ __launch_bounds__(256) void quant_act(
    const float* __restrict__ src, int8_t* __restrict__ q, float* __restrict__ s)
{
    const int row = blockIdx.x * 8 + (threadIdx.x >> 5);
    const int lane = threadIdx.x & 31;
    const float4* rp = (const float4*)(src + (size_t)row * 512);

    float4 v[4];
    float m = 0.0f;
#pragma unroll
    for (int i = 0; i < 4; i++) {
        v[i] = rp[i * 32 + lane];
        m = fmaxf(m, fmaxf(fmaxf(fabsf(v[i].x), fabsf(v[i].y)),
                           fmaxf(fabsf(v[i].z), fabsf(v[i].w))));
    }
#pragma unroll
    for (int o = 16; o > 0; o >>= 1)
        m = fmaxf(m, __shfl_xor_sync(0xffffffffu, m, o));

    const float inv = (m > 0.0f) ? 127.0f / m : 0.0f;
    if (lane == 0) s[row] = m * (1.0f / 127.0f);

    int8_t* q1p = q + (size_t)row * 1024;
    int8_t* q2p = q1p + 512;
#pragma unroll
    for (int i = 0; i < 4; i++) {
        const float* f = &v[i].x;
        char4 c1, c2;
        signed char* p1 = &c1.x;
        signed char* p2 = &c2.x;
#pragma unroll
        for (int u = 0; u < 4; u++) {
            const float t = f[u] * inv;
            const float a = rintf(t);
            const float b = rintf((t - a) * 254.0f);
            p1[u] = (signed char)(int)a;
            p2[u] = (signed char)(int)b;
        }
        ((char4*)q1p)[i * 32 + lane] = c1;
        ((char4*)q2p)[i * 32 + lane] = c2;
    }
}

// ---------------- transpose + per-column two-plane int8 weight quant --------
__global__ __launch_bounds__(256) void quant_w(
    const float* __restrict__ W, int8_t* __restrict__ q, float* __restrict__ s, int N)
{
    __shared__ float wm[8][32];
    __shared__ float invs[32];
    __shared__ int8_t qs[32][1040];

    const int n0 = blockIdx.x * 32;
    const int tx = threadIdx.x & 31;
    const int wy = threadIdx.x >> 5;
    const int n = n0 + tx;
    const bool ok = n < N;

    float m = 0.0f;
    for (int k = wy; k < 512; k += 8) {
        const float v = ok ? W[(size_t)k * N + n] : 0.0f;
        m = fmaxf(m, fabsf(v));
    }
    wm[wy][tx] = m;
    __syncthreads();
    if (threadIdx.x < 32) {
        float mm = wm[0][threadIdx.x];
#pragma unroll
        for (int w = 1; w < 8; w++) mm = fmaxf(mm, wm[w][threadIdx.x]);
        invs[threadIdx.x] = (mm > 0.0f) ? 127.0f / mm : 0.0f;
        s[n0 + threadIdx.x] = mm * (1.0f / 127.0f);
    }
    __syncthreads();

    const float inv = invs[tx];
    for (int k = wy; k < 512; k += 8) {
        const float v = ok ? W[(size_t)k * N + n] : 0.0f;
        const float t = v * inv;
        const float a = rintf(t);
        const float b = rintf((t - a) * 254.0f);
        qs[tx][k] = (int8_t)(int)a;
        qs[tx][512 + k] = (int8_t)(int)b;
    }
    __syncthreads();

#pragma unroll
    for (int i = 0; i < 8; i++) {
        const int idx = threadIdx.x + i * 256;
        const int row = idx >> 6;
        const int c = (idx & 63) * 16;
        *(uint4*)(q + (size_t)(n0 + row) * 1024 + c) = *(uint4*)(&qs[row][c]);
    }
}

// ---------------- sd + tree combine -----------------------------------------
__global__ __launch_bounds__(128) void sd_combine_kernel(
    const float* __restrict__ pse, const float* __restrict__ psx,
    const float* __restrict__ psf, const float* __restrict__ lnc,
    float* __restrict__ out)
{
    __shared__ float s_sd[NNODES];
    __shared__ float coeff[NLEAVES];
    const int b = blockIdx.x;
    const int tid = threadIdx.x;

    if (tid < NNODES) {
        const size_t base = ((size_t)b * NNODES + tid) * 16;
        float se = 0.f, sx = 0.f, sf = 0.f;
#pragma unroll
        for (int q = 0; q < 16; q++) {
            se += pse[base + q]; sx += psx[base + q]; sf += psf[base + q];
        }
        const float z = (sx - sf) / se;
        s_sd[tid] = 1.0f / (1.0f + expf(-z));
    }
    __syncthreads();
    if (tid < NLEAVES) {
        const int l = tid;
        float p, c;
        p = s_sd[0];            c  = ((l >> 3) & 1) ? 1.0f - p : p;
        p = s_sd[1 + (l >> 3)]; c *= ((l >> 2) & 1) ? 1.0f - p : p;
        p = s_sd[3 + (l >> 2)]; c *= ((l >> 1) & 1) ? 1.0f - p : p;
        p = s_sd[7 + (l >> 1)]; c *= (l & 1)        ? 1.0f - p : p;
        coeff[l] = c;
    }
    __syncthreads();
    if (tid < CC) {
        const float* lp = lnc + (size_t)b * (NLEAVES * CC) + tid;
        float acc = 0.0f;
#pragma unroll
        for (int l = 0; l < NLEAVES; l++) acc += coeff[l] * lp[l * CC];
        out[b * CC + tid] = acc;
    }
}

// ===========================================================================
extern "C" void kernel_launch(void* const* d_in, const int* in_sizes, int n_in,
                              void* d_out, int out_size)
{
    const float* x    = (const float*)d_in[0];
    const float* w_in = (const float*)d_in[1];
    const float* b_in = (const float*)d_in[2];
    const float* g0   = (const float*)d_in[3];
    const float* be0  = (const float*)d_in[4];
    const float* bw1  = (const float*)d_in[5];
    const float* bb1  = (const float*)d_in[6];
    const float* bg1  = (const float*)d_in[7];
    const float* bbe1 = (const float*)d_in[8];
    const float* bw2  = (const float*)d_in[9];
    const float* bb2  = (const float*)d_in[10];
    const float* bg2  = (const float*)d_in[11];
    const float* bbe2 = (const float*)d_in[12];
    const float* w_fi = (const float*)d_in[13];
    const float* b_fi = (const float*)d_in[14];
    const float* w_fs = (const float*)d_in[15];
    const float* b_fs = (const float*)d_in[16];
    const float* w_lc = (const float*)d_in[17];
    const float* b_lc = (const float*)d_in[18];
    float* out = (float*)d_out;

    int8_t *qact, *qwi, *qw1, *qw2, *qwfi, *qwfs, *qwlc;
    float *sact, *swi, *sw1, *sw2, *swfi, *swfs, *swlc;
    float *h0, *h1, *ht, *lc, *pse, *psx, *psf;
    cudaGetSymbolAddress((void**)&qact, g_qact); cudaGetSymbolAddress((void**)&sact, g_sact);
    cudaGetSymbolAddress((void**)&qwi, g_qwi);   cudaGetSymbolAddress((void**)&swi, g_swi);
    cudaGetSymbolAddress((void**)&qw1, g_qw1);   cudaGetSymbolAddress((void**)&sw1, g_sw1);
    cudaGetSymbolAddress((void**)&qw2, g_qw2);   cudaGetSymbolAddress((void**)&sw2, g_sw2);
    cudaGetSymbolAddress((void**)&qwfi, g_qwfi); cudaGetSymbolAddress((void**)&swfi, g_swfi);
    cudaGetSymbolAddress((void**)&qwfs, g_qwfs); cudaGetSymbolAddress((void**)&swfs, g_swfs);
    cudaGetSymbolAddress((void**)&qwlc, g_qwlc); cudaGetSymbolAddress((void**)&swlc, g_swlc);
    cudaGetSymbolAddress((void**)&h0, g_h0);     cudaGetSymbolAddress((void**)&h1, g_h1);
    cudaGetSymbolAddress((void**)&ht, g_ht);     cudaGetSymbolAddress((void**)&lc, g_lc);
    cudaGetSymbolAddress((void**)&pse, g_pse);
    cudaGetSymbolAddress((void**)&psx, g_psx);
    cudaGetSymbolAddress((void**)&psf, g_psf);

    cudaFuncSetAttribute(gemm_i8<0>, cudaFuncAttributeMaxDynamicSharedMemorySize, SMEM_G);
    cudaFuncSetAttribute(gemm_i8<1>, cudaFuncAttributeMaxDynamicSharedMemorySize, SMEM_G);
    cudaFuncSetAttribute(gemm_i8<2>, cudaFuncAttributeMaxDynamicSharedMemorySize, SMEM_G);
    cudaFuncSetAttribute(gemm_i8<3>, cudaFuncAttributeMaxDynamicSharedMemorySize, SMEM_G);
    cudaFuncSetAttribute(gemm_fifs_i8, cudaFuncAttributeMaxDynamicSharedMemorySize, SMEM_F);

    const dim3 g512(HH / 128, BQ / 128);
    const dim3 gfi(NFI / 128, BQ / 128);      // (60, 64): 2 row-blocks per CTA
    const dim3 glc(NLCP / 128, BQ / 128);
    const int QAB = BQ / 8;

    // ---- side stream: weight quant + lc GEMM (overlaps the main chain) ----
    cudaStream_t s2;
    cudaStreamCreateWithFlags(&s2, cudaStreamNonBlocking);
    cudaEvent_t evFork, evA, evB, evC, evD, evE, evF, evG, evH;
    cudaEventCreateWithFlags(&evFork, cudaEventDisableTiming);
    cudaEventCreateWithFlags(&evA, cudaEventDisableTiming);
    cudaEventCreateWithFlags(&evB, cudaEventDisableTiming);
    cudaEventCreateWithFlags(&evC, cudaEventDisableTiming);
    cudaEventCreateWithFlags(&evD, cudaEventDisableTiming);
    cudaEventCreateWithFlags(&evE, cudaEventDisableTiming);
    cudaEventCreateWithFlags(&evF, cudaEventDisableTiming);
    cudaEventCreateWithFlags(&evG, cudaEventDisableTiming);
    cudaEventCreateWithFlags(&evH, cudaEventDisableTiming);

    cudaEventRecord(evFork, 0);
    cudaStreamWaitEvent(s2, evFork, 0);

    quant_act<<<QAB, 256>>>(x, qact, sact);
    quant_w<<<HH / 32, 256, 0, s2>>>(w_in, qwi, swi, HH);
    cudaEventRecord(evA, s2);
    quant_w<<<HH / 32, 256, 0, s2>>>(bw1, qw1, sw1, HH);
    cudaEventRecord(evB, s2);
    cudaStreamWaitEvent(0, evA, 0);
    gemm_i8<1><<<g512, 256, SMEM_G>>>(qact, sact, qwi, swi,
        h0, HH, b_in, g0, be0, nullptr);
    quant_act<<<QAB, 256>>>(h0, qact, sact);
    quant_w<<<HH / 32, 256, 0, s2>>>(bw2, qw2, sw2, HH);
    cudaEventRecord(evC, s2);
    quant_w<<<HH / 32, 256, 0, s2>>>(bw1 + HH * HH, qw1 + (size_t)HH * 1024, sw1 + HH, HH);
    cudaEventRecord(evD, s2);
    quant_w<<<HH / 32, 256, 0, s2>>>(bw2 + HH * HH, qw2 + (size_t)HH * 1024, sw2 + HH, HH);
    cudaEventRecord(evE, s2);
    quant_w<<<NFI / 32, 256, 0, s2>>>(w_fi, qwfi, swfi, NFI);
    quant_w<<<NFI / 32, 256, 0, s2>>>(w_fs, qwfs, swfs, NFI);
    quant_w<<<NLCP / 32, 256, 0, s2>>>(w_lc, qwlc, swlc, NLC);
    cudaEventRecord(evF, s2);

    cudaStreamWaitEvent(0, evB, 0);
    gemm_i8<2><<<g512, 256, SMEM_G>>>(qact, sact, qw1, sw1,
        ht, HH, bb1, bg1, bbe1, nullptr);
    quant_act<<<QAB, 256>>>(ht, qact, sact);
    cudaStreamWaitEvent(0, evC, 0);
    gemm_i8<3><<<g512, 256, SMEM_G>>>(qact, sact, qw2, sw2,
        h1, HH, bb2, bg2, bbe2, h0);
    quant_act<<<QAB, 256>>>(h1, qact, sact);
    cudaStreamWaitEvent(0, evD, 0);
    gemm_i8<2><<<g512, 256, SMEM_G>>>(qact, sact, qw1 + (size_t)HH * 1024, sw1 + HH,
        ht, HH, bb1 + HH, bg1 + HH, bbe1 + HH, nullptr);
    quant_act<<<QAB, 256>>>(ht, qact, sact);
    cudaStreamWaitEvent(0, evE, 0);
    gemm_i8<3><<<g512, 256, SMEM_G>>>(qact, sact, qw2 + (size_t)HH * 1024, sw2 + HH,
        h0, HH, bb2 + HH, bg2 + HH, bbe2 + HH, h1);
    cudaStreamWaitEvent(0, evF, 0);
    quant_act<<<QAB, 256>>>(h0, qact, sact);
    cudaEventRecord(evG, 0);

    // lc GEMM on side stream, concurrent with fifs
    cudaStreamWaitEvent(s2, evG, 0);
    gemm_i8<0><<<glc, 256, SMEM_G, s2>>>(qact, sact, qwlc, swlc,
        lc, NLC, b_lc, nullptr, nullptr, nullptr);
    cudaEventRecord(evH, s2);

    gemm_fifs_i8<<<gfi, 256, SMEM_F>>>(qact, sact, qwfi, swfi, qwfs, swfs,
                                       x, b_fi, b_fs, pse, psx, psf);
    cudaStreamWaitEvent(0, evH, 0);
    sd_combine_kernel<<<BQ, 128>>>(pse, psx, psf, lc, out);
}

// round 15
// speedup vs baseline: 1.1818x; 1.0222x over previous
#include <cuda_runtime.h>
#include <cstdint>
#include <math.h>

// ===========================================================================
// DTHyperNet via int8 IMMA digit-planes (mma.sync.m16n8k32.s8, s32 accum)
//   v = (rowmax/127) * (q1 + q2/254);  D = sA*sB*(P11 + (P12+P21)/254)
// Row-split software pipeline: trunk GEMMs + quant_act split into 4096-row
// halves so quantization hides behind the other half's GEMM.
// Streams/events are created once (lazy init) so graph teardown returns to
// the pre-capture memory baseline.
// ===========================================================================

#define BQ 8192
#define HALF 4096
#define FF 512
#define HH 512
#define CC 100
#define NNODES 15
#define NLEAVES 16
#define NFI 7680
#define NLC 1600
#define NLCP 1664
#define EPSV 1e-5f
#define INV254 (1.0f / 254.0f)

// -------------------- device scratch (no allocations allowed) --------------
__device__ int8_t g_qact[(size_t)BQ * 1024];
__device__ float  g_sact[BQ];
__device__ float  g_h0[(size_t)BQ * HH];
__device__ float  g_h1[(size_t)BQ * HH];
__device__ float  g_ht[(size_t)BQ * HH];
__device__ int8_t g_qwi[(size_t)HH * 1024];
__device__ int8_t g_qw1[(size_t)2 * HH * 1024];
__device__ int8_t g_qw2[(size_t)2 * HH * 1024];
__device__ int8_t g_qwfi[(size_t)NFI * 1024];
__device__ int8_t g_qwfs[(size_t)NFI * 1024];
__device__ int8_t g_qwlc[(size_t)NLCP * 1024];
__device__ float  g_swi[HH], g_sw1[2 * HH], g_sw2[2 * HH];
__device__ float  g_swfi[NFI], g_swfs[NFI], g_swlc[NLCP];
__device__ float  g_lc[(size_t)BQ * NLC];
__device__ float  g_pse[(size_t)BQ * NNODES * 16];
__device__ float  g_psx[(size_t)BQ * NNODES * 16];
__device__ float  g_psf[(size_t)BQ * NNODES * 16];

// -------------------- PTX helpers (sm_80 baseline only) --------------------
__device__ __forceinline__ uint32_t smem_u32(const void* p) {
    uint32_t a;
    asm("{ .reg .u64 t; cvta.to.shared.u64 t, %1; cvt.u32.u64 %0, t; }"
        : "=r"(a) : "l"(p));
    return a;
}
#define CP16(dst, src) \
    asm volatile("cp.async.cg.shared.global [%0], [%1], 16;" :: "r"(dst), "l"(src))
#define CP_COMMIT() asm volatile("cp.async.commit_group;" ::: "memory")
#define CP_WAIT0() asm volatile("cp.async.wait_group 0;" ::: "memory")
#define CP_WAIT1() asm volatile("cp.async.wait_group 1;" ::: "memory")

__device__ __forceinline__ void ldsm4(uint32_t* r, uint32_t addr) {
    asm volatile("ldmatrix.sync.aligned.m8n8.x4.shared.b16 {%0,%1,%2,%3}, [%4];"
                 : "=r"(r[0]), "=r"(r[1]), "=r"(r[2]), "=r"(r[3]) : "r"(addr));
}
__device__ __forceinline__ void mma_s8(int* c, const uint32_t* a,
                                       uint32_t b0, uint32_t b1) {
    asm volatile(
        "mma.sync.aligned.m16n8k32.row.col.s32.s8.s8.s32 "
        "{%0,%1,%2,%3}, {%4,%5,%6,%7}, {%8,%9}, {%0,%1,%2,%3};"
        : "+r"(c[0]), "+r"(c[1]), "+r"(c[2]), "+r"(c[3])
        : "r"(a[0]), "r"(a[1]), "r"(a[2]), "r"(a[3]), "r"(b0), "r"(b1));
}

// 128-byte K-chunk per stage, padded row stride 144 bytes
#define ROWB 144
#define TILEB (128 * ROWB)
#define TILEA64 (64 * ROWB)
#define NSTAGE 3
#define KSTAGES 12
#define PASS1 4
#define SMEM_G (NSTAGE * 2 * TILEB)            // 110592
#define FSTAGE (TILEA64 + 2 * TILEB)           // 46080
#define SMEM_F (NSTAGE * FSTAGE)               // 138240

// ===========================================================================
// Generic int8 GEMM (trunk + lc): 256 thr, 8 warps (2x4), 64x32 warp tiles.
// ===========================================================================
template <int EPI>
__global__ __launch_bounds__(256) void gemm_i8(
    const int8_t* __restrict__ qA, const float* __restrict__ sA,
    const int8_t* __restrict__ qB, const float* __restrict__ sB,
    float* __restrict__ C, int Nout, int row_base,
    const float* __restrict__ bias, const float* __restrict__ gamma,
    const float* __restrict__ beta, const float* __restrict__ resid)
{
    extern __shared__ char dsm[];
    const uint32_t sb = smem_u32(dsm);

    const int tid = threadIdx.x;
    const int lane = tid & 31;
    const int wid = tid >> 5;
    const int warp_m = wid >> 2;
    const int warp_n = wid & 3;
    const int bm = row_base + blockIdx.y * 128;
    const int bn = blockIdx.x * 128;

    const int8_t* Asrc[3] = { qA + (size_t)bm * 1024,
                              qA + (size_t)bm * 1024,
                              qA + (size_t)bm * 1024 + 512 };
    const int8_t* Bsrc[3] = { qB + (size_t)bn * 1024,
                              qB + (size_t)bn * 1024 + 512,
                              qB + (size_t)bn * 1024 };

    const int arow = (lane & 7) + ((lane >> 3) & 1) * 8;
    const int asel = lane >> 4;
    const int brow = ((lane >> 4) & 1) * 8 + (lane & 7);
    const int bsel = (lane >> 3) & 1;
    const uint32_t a_lane = (uint32_t)(warp_m * 64 + arow) * ROWB;
    const uint32_t b_lane = (uint32_t)(warp_n * 32 + brow) * ROWB;

    int acc0[4][4][4], acc1[4][4][4];
#pragma unroll
    for (int i = 0; i < 4; i++)
#pragma unroll
        for (int j = 0; j < 4; j++)
#pragma unroll
            for (int u = 0; u < 4; u++) { acc0[i][j][u] = 0; acc1[i][j][u] = 0; }

    auto load_stage = [&](int s, int buf) {
        const int p = s >> 2;
        const int ko = (s & 3) * 128;
        const uint32_t ab = sb + buf * (2 * TILEB);
        const uint32_t bb = ab + TILEB;
        const int8_t* As = Asrc[p] + ko;
        const int8_t* Bs = Bsrc[p] + ko;
#pragma unroll
        for (int i = 0; i < 4; i++) {
            const int idx = tid + i * 256;
            const int r = idx >> 3, c = (idx & 7) * 16;
            CP16(ab + r * ROWB + c, As + (size_t)r * 1024 + c);
            CP16(bb + r * ROWB + c, Bs + (size_t)r * 1024 + c);
        }
    };

    load_stage(0, 0); CP_COMMIT();
    load_stage(1, 1); CP_COMMIT();

    int buf = 0;
    auto stage_body = [&](int s, int (&acc)[4][4][4]) {
        if (s + 2 < KSTAGES) { CP_WAIT1(); } else { CP_WAIT0(); }
        __syncthreads();
        if (s + 2 < KSTAGES) {
            int nb = buf + 2; if (nb >= NSTAGE) nb -= NSTAGE;
            load_stage(s + 2, nb);
            CP_COMMIT();
        }
        const uint32_t ab = sb + buf * (2 * TILEB);
        const uint32_t bb = ab + TILEB;
#pragma unroll
        for (int kh = 0; kh < 4; kh++) {
            uint32_t af[4][4], bf[2][4];
            const uint32_t kadd = kh * 32;
#pragma unroll
            for (int m = 0; m < 4; m++)
                ldsm4(af[m], ab + a_lane + m * (16 * ROWB) + kadd + asel * 16);
#pragma unroll
            for (int n2 = 0; n2 < 2; n2++)
                ldsm4(bf[n2], bb + b_lane + n2 * (16 * ROWB) + kadd + bsel * 16);
#pragma unroll
            for (int m = 0; m < 4; m++)
#pragma unroll
                for (int n = 0; n < 4; n++)
                    mma_s8(acc[m][n], af[m],
                           bf[n >> 1][(n & 1) * 2 + 0], bf[n >> 1][(n & 1) * 2 + 1]);
        }
        buf++; if (buf == NSTAGE) buf = 0;
    };

    for (int s = 0; s < PASS1; s++) stage_body(s, acc0);
    for (int s = PASS1; s < KSTAGES; s++) stage_body(s, acc1);

    // -------- epilogue --------
    const float RS = rsqrtf(1.0f + EPSV);
    const int lm = lane >> 2;
    const int ln2 = (lane & 3) * 2;
    const int row0 = bm + warp_m * 64;
    const int col0 = bn + warp_n * 32;

#pragma unroll
    for (int m = 0; m < 4; m++) {
        const int r_lo = row0 + m * 16 + lm;
        const int r_hi = r_lo + 8;
        const float sa0 = sA[r_lo], sa1 = sA[r_hi];
#pragma unroll
        for (int n = 0; n < 4; n++) {
            const int gn = col0 + n * 8 + ln2;
            if (EPI == 0 && gn >= Nout) continue;
            const float sb0 = sB[gn], sb1 = sB[gn + 1];
            const int* c0 = acc0[m][n];
            const int* c1 = acc1[m][n];
            float v[4];
            v[0] = ((float)c0[0] + (float)c1[0] * INV254) * (sa0 * sb0);
            v[1] = ((float)c0[1] + (float)c1[1] * INV254) * (sa0 * sb1);
            v[2] = ((float)c0[2] + (float)c1[2] * INV254) * (sa1 * sb0);
            v[3] = ((float)c0[3] + (float)c1[3] * INV254) * (sa1 * sb1);
            const float bz0 = bias[gn], bz1 = bias[gn + 1];
            if (EPI == 0) {
                *(float2*)(C + (size_t)r_lo * Nout + gn) = make_float2(v[0] + bz0, v[1] + bz1);
                *(float2*)(C + (size_t)r_hi * Nout + gn) = make_float2(v[2] + bz0, v[3] + bz1);
            } else {
                const float s0 = gamma[gn] * RS, s1 = gamma[gn + 1] * RS;
                const float e0 = beta[gn], e1 = beta[gn + 1];
                v[0] = (v[0] + bz0) * s0 + e0; v[1] = (v[1] + bz1) * s1 + e1;
                v[2] = (v[2] + bz0) * s0 + e0; v[3] = (v[3] + bz1) * s1 + e1;
#pragma unroll
                for (int u = 0; u < 4; u++) {
                    if (EPI == 1) v[u] = fmaxf(v[u], 0.0f);
                    else v[u] = 0.5f * v[u] * (1.0f + erff(v[u] * 0.70710678118654752f));
                }
                if (EPI == 3) {
                    const float2 r0 = *(const float2*)(resid + (size_t)r_lo * HH + gn);
                    const float2 r1 = *(const float2*)(resid + (size_t)r_hi * HH + gn);
                    v[0] += r0.x; v[1] += r0.y; v[2] += r1.x; v[3] += r1.y;
                }
                *(float2*)(C + (size_t)r_lo * HH + gn) = make_float2(v[0], v[1]);
                *(float2*)(C + (size_t)r_hi * HH + gn) = make_float2(v[2], v[3]);
            }
        }
    }
}

// ===========================================================================
// Fused int8 fi/fs head + node reduction. 64x128 tile, 256 thr, 8 warps (2x4),
// two 64-row blocks per CTA. grid (60, 32) per 4096-row half.
// ===========================================================================
__global__ __launch_bounds__(256, 1) void gemm_fifs_i8(
    const int8_t* __restrict__ qA, const float* __restrict__ sA,
    const int8_t* __restrict__ qBi, const float* __restrict__ sBi,
    const int8_t* __restrict__ qBs, const float* __restrict__ sBs,
    const float* __restrict__ x, int row_base,
    const float* __restrict__ b_fi, const float* __restrict__ b_fs,
    float* __restrict__ pse, float* __restrict__ psx, float* __restrict__ psf)
{
    extern __shared__ char dsm[];
    const uint32_t sb = smem_u32(dsm);

    const int tid = threadIdx.x;
    const int lane = tid & 31;
    const int wid = tid >> 5;
    const int warp_m = wid >> 2;
    const int warp_n = wid & 3;
    const int ct = blockIdx.x;
    const int bn = ct * 128;
    const int node = ct >> 2;
    const int slice = (ct & 3) * 4 + warp_n;
    const int xbase = (ct & 3) * 128 + warp_n * 32;

    const int8_t* BiP[3] = { qBi + (size_t)bn * 1024,
                             qBi + (size_t)bn * 1024 + 512,
                             qBi + (size_t)bn * 1024 };
    const int8_t* BsP[3] = { qBs + (size_t)bn * 1024,
                             qBs + (size_t)bn * 1024 + 512,
                             qBs + (size_t)bn * 1024 };

    const int arow = (lane & 7) + ((lane >> 3) & 1) * 8;
    const int asel = lane >> 4;
    const int brow = ((lane >> 4) & 1) * 8 + (lane & 7);
    const int bsel = (lane >> 3) & 1;
    const uint32_t a_lane = (uint32_t)(warp_m * 32 + arow) * ROWB;
    const uint32_t b_lane = (uint32_t)(warp_n * 32 + brow) * ROWB;

    const int lm = lane >> 2;
    const int ln2 = (lane & 3) * 2;

    for (int rb = 0; rb < 2; rb++) {
        const int bm = row_base + (blockIdx.y * 2 + rb) * 64;
        const int8_t* Asrc[3] = { qA + (size_t)bm * 1024,
                                  qA + (size_t)bm * 1024,
                                  qA + (size_t)bm * 1024 + 512 };

        int aI0[2][4][4], aI1[2][4][4], aS0[2][4][4], aS1[2][4][4];
#pragma unroll
        for (int i = 0; i < 2; i++)
#pragma unroll
            for (int j = 0; j < 4; j++)
#pragma unroll
                for (int u = 0; u < 4; u++) {
                    aI0[i][j][u] = 0; aI1[i][j][u] = 0;
                    aS0[i][j][u] = 0; aS1[i][j][u] = 0;
                }

        auto load_stage = [&](int s, int buf) {
            const int p = s >> 2;
            const int ko = (s & 3) * 128;
            const uint32_t ab = sb + buf * FSTAGE;
            const uint32_t ib = ab + TILEA64;
            const uint32_t qb = ib + TILEB;
#pragma unroll
            for (int i = 0; i < 2; i++) {
                const int idx = tid + i * 256;
                const int r = idx >> 3, c = (idx & 7) * 16;
                CP16(ab + r * ROWB + c, Asrc[p] + ko + (size_t)r * 1024 + c);
            }
#pragma unroll
            for (int i = 0; i < 4; i++) {
                const int idx = tid + i * 256;
                const int r = idx >> 3, c = (idx & 7) * 16;
                CP16(ib + r * ROWB + c, BiP[p] + ko + (size_t)r * 1024 + c);
                CP16(qb + r * ROWB + c, BsP[p] + ko + (size_t)r * 1024 + c);
            }
        };

        load_stage(0, 0); CP_COMMIT();
        load_stage(1, 1); CP_COMMIT();

        int buf = 0;
        auto stage_body = [&](int s, int (&aI)[2][4][4], int (&aS)[2][4][4]) {
            if (s + 2 < KSTAGES) { CP_WAIT1(); } else { CP_WAIT0(); }
            __syncthreads();
            if (s + 2 < KSTAGES) {
                int nb = buf + 2; if (nb >= NSTAGE) nb -= NSTAGE;
                load_stage(s + 2, nb);
                CP_COMMIT();
            }
            const uint32_t ab = sb + buf * FSTAGE;
            const uint32_t ib = ab + TILEA64;
            const uint32_t qb = ib + TILEB;
#pragma unroll
            for (int kh = 0; kh < 4; kh++) {
                uint32_t af[2][4], bi[2][4], bq[2][4];
                const uint32_t kadd = kh * 32;
#pragma unroll
                for (int m = 0; m < 2; m++)
                    ldsm4(af[m], ab + a_lane + m * (16 * ROWB) + kadd + asel * 16);
#pragma unroll
                for (int n2 = 0; n2 < 2; n2++) {
                    ldsm4(bi[n2], ib + b_lane + n2 * (16 * ROWB) + kadd + bsel * 16);
                    ldsm4(bq[n2], qb + b_lane + n2 * (16 * ROWB) + kadd + bsel * 16);
                }
#pragma unroll
                for (int m = 0; m < 2; m++)
#pragma unroll
                    for (int n = 0; n < 4; n++) {
                        mma_s8(aI[m][n], af[m],
                               bi[n >> 1][(n & 1) * 2 + 0], bi[n >> 1][(n & 1) * 2 + 1]);
                        mma_s8(aS[m][n], af[m],
                               bq[n >> 1][(n & 1) * 2 + 0], bq[n >> 1][(n & 1) * 2 + 1]);
                    }
            }
            buf++; if (buf == NSTAGE) buf = 0;
        };

        for (int s = 0; s < PASS1; s++) stage_body(s, aI0, aS0);
        for (int s = PASS1; s < KSTAGES; s++) stage_body(s, aI1, aS1);

        // -------- fused reduction epilogue --------
        const int row0 = bm + warp_m * 32;
        const int col0 = bn + warp_n * 32;

        float sa[2][2];
#pragma unroll
        for (int m = 0; m < 2; m++) {
            sa[m][0] = sA[row0 + m * 16 + lm];
            sa[m][1] = sA[row0 + m * 16 + lm + 8];
        }

        float se[4], sx[4], sf[4];
#pragma unroll
        for (int i = 0; i < 4; i++) { se[i] = 0.f; sx[i] = 0.f; sf[i] = 0.f; }

#pragma unroll
        for (int n = 0; n < 4; n++) {
            const int gn = col0 + n * 8 + ln2;
            const int xc = xbase + n * 8 + ln2;
            const float bi0 = b_fi[gn], bi1 = b_fi[gn + 1];
            const float bs0 = b_fs[gn], bs1 = b_fs[gn + 1];
            const float si0 = sBi[gn], si1 = sBi[gn + 1];
            const float ss0 = sBs[gn], ss1 = sBs[gn + 1];
#pragma unroll
            for (int m = 0; m < 2; m++) {
                const int r_lo = row0 + m * 16 + lm;
                const int r_hi = r_lo + 8;
                const int* i0 = aI0[m][n]; const int* i1 = aI1[m][n];
                const int* s0 = aS0[m][n]; const int* s1 = aS1[m][n];
                const float fi0 = ((float)i0[0] + (float)i1[0] * INV254) * (sa[m][0] * si0) + bi0;
                const float fi1 = ((float)i0[1] + (float)i1[1] * INV254) * (sa[m][0] * si1) + bi1;
                const float fi2 = ((float)i0[2] + (float)i1[2] * INV254) * (sa[m][1] * si0) + bi0;
                const float fi3 = ((float)i0[3] + (float)i1[3] * INV254) * (sa[m][1] * si1) + bi1;
                const float fs0 = ((float)s0[0] + (float)s1[0] * INV254) * (sa[m][0] * ss0) + bs0;
                const float fs1 = ((float)s0[1] + (float)s1[1] * INV254) * (sa[m][0] * ss1) + bs1;
                const float fs2 = ((float)s0[2] + (float)s1[2] * INV254) * (sa[m][1] * ss0) + bs0;
                const float fs3 = ((float)s0[3] + (float)s1[3] * INV254) * (sa[m][1] * ss1) + bs1;
                const float e0 = __expf(fi0);
                const float e1 = __expf(fi1);
                const float e2 = __expf(fi2);
                const float e3 = __expf(fi3);
                const float2 x0 = *(const float2*)(x + (size_t)r_lo * FF + xc);
                const float2 x1 = *(const float2*)(x + (size_t)r_hi * FF + xc);
                se[m * 2 + 0] += e0 + e1;
                se[m * 2 + 1] += e2 + e3;
                sx[m * 2 + 0] += e0 * x0.x + e1 * x0.y;
                sx[m * 2 + 1] += e2 * x1.x + e3 * x1.y;
                sf[m * 2 + 0] += e0 * fs0 + e1 * fs1;
                sf[m * 2 + 1] += e2 * fs2 + e3 * fs3;
            }
        }

#pragma unroll
        for (int i = 0; i < 4; i++) {
            se[i] += __shfl_xor_sync(0xffffffffu, se[i], 1);
            se[i] += __shfl_xor_sync(0xffffffffu, se[i], 2);
            sx[i] += __shfl_xor_sync(0xffffffffu, sx[i], 1);
            sx[i] += __shfl_xor_sync(0xffffffffu, sx[i], 2);
            sf[i] += __shfl_xor_sync(0xffffffffu, sf[i], 1);
            sf[i] += __shfl_xor_sync(0xffffffffu, sf[i], 2);
        }
        if ((lane & 3) == 0) {
#pragma unroll
            for (int i = 0; i < 4; i++) {
                const int row = row0 + (i >> 1) * 16 + lm + (i & 1) * 8;
                const size_t o = ((size_t)row * NNODES + node) * 16 + slice;
                pse[o] = se[i]; psx[o] = sx[i]; psf[o] = sf[i];
            }
        }
    }
}

// ---------------- per-row two-plane int8 quantization of activations --------
__global__ __launch_bounds__(256) void quant_act(
    const float* __restrict__ src, int8_t* __restrict__ q, float* __restrict__ s,
    int row_base)
{
    const int row = row_base + blockIdx.x * 8 + (threadIdx.x >> 5);
    const int lane = threadIdx.x & 31;
    const float4* rp = (const float4*)(src + (size_t)row * 512);

    float4 v[4];
    float m = 0.0f;
#pragma unroll
    for (int i = 0; i < 4; i++) {
        v[i] = rp[i * 32 + lane];
        m = fmaxf(m, fmaxf(fmaxf(fabsf(v[i].x), fabsf(v[i].y)),
                           fmaxf(fabsf(v[i].z), fabsf(v[i].w))));
    }
#pragma unroll
    for (int o = 16; o > 0; o >>= 1)
        m = fmaxf(m, __shfl_xor_sync(0xffffffffu, m, o));

    const float inv = (m > 0.0f) ? 127.0f / m : 0.0f;
    if (lane == 0) s[row] = m * (1.0f / 127.0f);

    int8_t* q1p = q + (size_t)row * 1024;
    int8_t* q2p = q1p + 512;
#pragma unroll
    for (int i = 0; i < 4; i++) {
        const float* f = &v[i].x;
        char4 c1, c2;
        signed char* p1 = &c1.x;
        signed char* p2 = &c2.x;
#pragma unroll
        for (int u = 0; u < 4; u++) {
            const float t = f[u] * inv;
            const float a = rintf(t);
            const float b = rintf((t - a) * 254.0f);
            p1[u] = (signed char)(int)a;
            p2[u] = (signed char)(int)b;
        }
        ((char4*)q1p)[i * 32 + lane] = c1;
        ((char4*)q2p)[i * 32 + lane] = c2;
    }
}

// ---------------- transpose + per-column two-plane int8 weight quant --------
__global__ __launch_bounds__(256) void quant_w(
    const float* __restrict__ W, int8_t* __restrict__ q, float* __restrict__ s, int N)
{
    __shared__ float wm[8][32];
    __shared__ float invs[32];
    __shared__ int8_t qs[32][1040];

    const int n0 = blockIdx.x * 32;
    const int tx = threadIdx.x & 31;
    const int wy = threadIdx.x >> 5;
    const int n = n0 + tx;
    const bool ok = n < N;

    float m = 0.0f;
    for (int k = wy; k < 512; k += 8) {
        const float v = ok ? W[(size_t)k * N + n] : 0.0f;
        m = fmaxf(m, fabsf(v));
    }
    wm[wy][tx] = m;
    __syncthreads();
    if (threadIdx.x < 32) {
        float mm = wm[0][threadIdx.x];
#pragma unroll
        for (int w = 1; w < 8; w++) mm = fmaxf(mm, wm[w][threadIdx.x]);
        invs[threadIdx.x] = (mm > 0.0f) ? 127.0f / mm : 0.0f;
        s[n0 + threadIdx.x] = mm * (1.0f / 127.0f);
    }
    __syncthreads();

    const float inv = invs[tx];
    for (int k = wy; k < 512; k += 8) {
        const float v = ok ? W[(size_t)k * N + n] : 0.0f;
        const float t = v * inv;
        const float a = rintf(t);
        const float b = rintf((t - a) * 254.0f);
        qs[tx][k] = (int8_t)(int)a;
        qs[tx][512 + k] = (int8_t)(int)b;
    }
    __syncthreads();

#pragma unroll
    for (int i = 0; i < 8; i++) {
        const int idx = threadIdx.x + i * 256;
        const int row = idx >> 6;
        const int c = (idx & 63) * 16;
        *(uint4*)(q + (size_t)(n0 + row) * 1024 + c) = *(uint4*)(&qs[row][c]);
    }
}

// ---------------- sd + tree combine -----------------------------------------
__global__ __launch_bounds__(128) void sd_combine_kernel(
    const float* __restrict__ pse, const float* __restrict__ psx,
    const float* __restrict__ psf, const float* __restrict__ lnc,
    float* __restrict__ out)
{
    __shared__ float s_sd[NNODES];
    __shared__ float coeff[NLEAVES];
    const int b = blockIdx.x;
    const int tid = threadIdx.x;

    if (tid < NNODES) {
        const size_t base = ((size_t)b * NNODES + tid) * 16;
        float se = 0.f, sx = 0.f, sf = 0.f;
#pragma unroll
        for (int q = 0; q < 16; q++) {
            se += pse[base + q]; sx += psx[base + q]; sf += psf[base + q];
        }
        const float z = (sx - sf) / se;
        s_sd[tid] = 1.0f / (1.0f + expf(-z));
    }
    __syncthreads();
    if (tid < NLEAVES) {
        const int l = tid;
        float p, c;
        p = s_sd[0];            c  = ((l >> 3) & 1) ? 1.0f - p : p;
        p = s_sd[1 + (l >> 3)]; c *= ((l >> 2) & 1) ? 1.0f - p : p;
        p = s_sd[3 + (l >> 2)]; c *= ((l >> 1) & 1) ? 1.0f - p : p;
        p = s_sd[7 + (l >> 1)]; c *= (l & 1)        ? 1.0f - p : p;
        coeff[l] = c;
    }
    __syncthreads();
    if (tid < CC) {
        const float* lp = lnc + (size_t)b * (NLEAVES * CC) + tid;
        float acc = 0.0f;
#pragma unroll
        for (int l = 0; l < NLEAVES; l++) acc += coeff[l] * lp[l * CC];
        out[b * CC + tid] = acc;
    }
}

// ===========================================================================
extern "C" void kernel_launch(void* const* d_in, const int* in_sizes, int n_in,
                              void* d_out, int out_size)
{
    const float* x    = (const float*)d_in[0];
    const float* w_in = (const float*)d_in[1];
    const float* b_in = (const float*)d_in[2];
    const float* g0   = (const float*)d_in[3];
    const float* be0  = (const float*)d_in[4];
    const float* bw1  = (const float*)d_in[5];
    const float* bb1  = (const float*)d_in[6];
    const float* bg1  = (const float*)d_in[7];
    const float* bbe1 = (const float*)d_in[8];
    const float* bw2  = (const float*)d_in[9];
    const float* bb2  = (const float*)d_in[10];
    const float* bg2  = (const float*)d_in[11];
    const float* bbe2 = (const float*)d_in[12];
    const float* w_fi = (const float*)d_in[13];
    const float* b_fi = (const float*)d_in[14];
    const float* w_fs = (const float*)d_in[15];
    const float* b_fs = (const float*)d_in[16];
    const float* w_lc = (const float*)d_in[17];
    const float* b_lc = (const float*)d_in[18];
    float* out = (float*)d_out;

    int8_t *qact, *qwi, *qw1, *qw2, *qwfi, *qwfs, *qwlc;
    float *sact, *swi, *sw1, *sw2, *swfi, *swfs, *swlc;
    float *h0, *h1, *ht, *lc, *pse, *psx, *psf;
    cudaGetSymbolAddress((void**)&qact, g_qact); cudaGetSymbolAddress((void**)&sact, g_sact);
    cudaGetSymbolAddress((void**)&qwi, g_qwi);   cudaGetSymbolAddress((void**)&swi, g_swi);
    cudaGetSymbolAddress((void**)&qw1, g_qw1);   cudaGetSymbolAddress((void**)&sw1, g_sw1);
    cudaGetSymbolAddress((void**)&qw2, g_qw2);   cudaGetSymbolAddress((void**)&sw2, g_sw2);
    cudaGetSymbolAddress((void**)&qwfi, g_qwfi); cudaGetSymbolAddress((void**)&swfi, g_swfi);
    cudaGetSymbolAddress((void**)&qwfs, g_qwfs); cudaGetSymbolAddress((void**)&swfs, g_swfs);
    cudaGetSymbolAddress((void**)&qwlc, g_qwlc); cudaGetSymbolAddress((void**)&swlc, g_swlc);
    cudaGetSymbolAddress((void**)&h0, g_h0);     cudaGetSymbolAddress((void**)&h1, g_h1);
    cudaGetSymbolAddress((void**)&ht, g_ht);     cudaGetSymbolAddress((void**)&lc, g_lc);
    cudaGetSymbolAddress((void**)&pse, g_pse);
    cudaGetSymbolAddress((void**)&psx, g_psx);
    cudaGetSymbolAddress((void**)&psf, g_psf);

    cudaFuncSetAttribute(gemm_i8<0>, cudaFuncAttributeMaxDynamicSharedMemorySize, SMEM_G);
    cudaFuncSetAttribute(gemm_i8<1>, cudaFuncAttributeMaxDynamicSharedMemorySize, SMEM_G);
    cudaFuncSetAttribute(gemm_i8<2>, cudaFuncAttributeMaxDynamicSharedMemorySize, SMEM_G);
    cudaFuncSetAttribute(gemm_i8<3>, cudaFuncAttributeMaxDynamicSharedMemorySize, SMEM_G);
    cudaFuncSetAttribute(gemm_fifs_i8, cudaFuncAttributeMaxDynamicSharedMemorySize, SMEM_F);

    const dim3 gH(HH / 128, HALF / 128);          // (4, 32) per half
    const dim3 gfiH(NFI / 128, HALF / 128);       // (60, 32) per half
    const dim3 glc(NLCP / 128, BQ / 128);
    const int QABH = HALF / 8;                    // 512 blocks per half

    // ---- streams/events created ONCE (first call = correctness run), so the
    // pre-capture memory baseline already includes their driver pools ----
    static cudaStream_t s2 = nullptr, s3 = nullptr;
    static cudaEvent_t evFork, evW[6], eg[10], eq[10], evLC;
    if (s2 == nullptr) {
        cudaStreamCreateWithFlags(&s2, cudaStreamNonBlocking);
        cudaStreamCreateWithFlags(&s3, cudaStreamNonBlocking);
        cudaEventCreateWithFlags(&evFork, cudaEventDisableTiming);
        for (int i = 0; i < 6; i++) cudaEventCreateWithFlags(&evW[i], cudaEventDisableTiming);
        for (int i = 0; i < 10; i++) cudaEventCreateWithFlags(&eg[i], cudaEventDisableTiming);
        for (int i = 0; i < 10; i++) cudaEventCreateWithFlags(&eq[i], cudaEventDisableTiming);
        cudaEventCreateWithFlags(&evLC, cudaEventDisableTiming);
    }

    cudaEventRecord(evFork, 0);
    cudaStreamWaitEvent(s2, evFork, 0);
    cudaStreamWaitEvent(s3, evFork, 0);

    // main: quantize x (both halves)
    quant_act<<<QABH, 256>>>(x, qact, sact, 0);
    quant_act<<<QABH, 256>>>(x, qact, sact, HALF);
    // s2: all weight quantizations
    quant_w<<<HH / 32, 256, 0, s2>>>(w_in, qwi, swi, HH);   cudaEventRecord(evW[0], s2);
    quant_w<<<HH / 32, 256, 0, s2>>>(bw1, qw1, sw1, HH);    cudaEventRecord(evW[1], s2);
    quant_w<<<HH / 32, 256, 0, s2>>>(bw2, qw2, sw2, HH);    cudaEventRecord(evW[2], s2);
    quant_w<<<HH / 32, 256, 0, s2>>>(bw1 + HH * HH, qw1 + (size_t)HH * 1024, sw1 + HH, HH);
    cudaEventRecord(evW[3], s2);
    quant_w<<<HH / 32, 256, 0, s2>>>(bw2 + HH * HH, qw2 + (size_t)HH * 1024, sw2 + HH, HH);
    cudaEventRecord(evW[4], s2);
    quant_w<<<NFI / 32, 256, 0, s2>>>(w_fi, qwfi, swfi, NFI);
    quant_w<<<NFI / 32, 256, 0, s2>>>(w_fs, qwfs, swfs, NFI);
    quant_w<<<NLCP / 32, 256, 0, s2>>>(w_lc, qwlc, swlc, NLC);
    cudaEventRecord(evW[5], s2);

    // ---- trunk: row-split pipelined halves (main = gemm, s3 = quant_act) ----
    const int8_t* qwp[5] = { qwi, qw1, qw2, qw1 + (size_t)HH * 1024, qw2 + (size_t)HH * 1024 };
    const float*  swp[5] = { swi, sw1, sw2, sw1 + HH, sw2 + HH };
    float* outs[5]  = { h0, ht, h1, ht, h0 };
    const float* res[5] = { nullptr, nullptr, h0, nullptr, h1 };
    const float* bia[5] = { b_in, bb1, bb2, bb1 + HH, bb2 + HH };
    const float* gam[5] = { g0, bg1, bg2, bg1 + HH, bg2 + HH };
    const float* bet[5] = { be0, bbe1, bbe2, bbe1 + HH, bbe2 + HH };
    const int    epi[5] = { 1, 2, 3, 2, 3 };

    for (int L = 0; L < 5; L++) {
        cudaStreamWaitEvent(0, evW[L], 0);
        if (L > 0) cudaStreamWaitEvent(0, eq[2 * (L - 1)], 0);
        // half 0
        switch (epi[L]) {
        case 1: gemm_i8<1><<<gH, 256, SMEM_G>>>(qact, sact, qwp[L], swp[L],
                    outs[L], HH, 0, bia[L], gam[L], bet[L], res[L]); break;
        case 2: gemm_i8<2><<<gH, 256, SMEM_G>>>(qact, sact, qwp[L], swp[L],
                    outs[L], HH, 0, bia[L], gam[L], bet[L], res[L]); break;
        default: gemm_i8<3><<<gH, 256, SMEM_G>>>(qact, sact, qwp[L], swp[L],
                    outs[L], HH, 0, bia[L], gam[L], bet[L], res[L]); break;
        }
        cudaEventRecord(eg[2 * L], 0);
        cudaStreamWaitEvent(s3, eg[2 * L], 0);
        quant_act<<<QABH, 256, 0, s3>>>(outs[L], qact, sact, 0);
        cudaEventRecord(eq[2 * L], s3);
        // half 1
        if (L > 0) cudaStreamWaitEvent(0, eq[2 * (L - 1) + 1], 0);
        switch (epi[L]) {
        case 1: gemm_i8<1><<<gH, 256, SMEM_G>>>(qact, sact, qwp[L], swp[L],
                    outs[L], HH, HALF, bia[L], gam[L], bet[L], res[L]); break;
        case 2: gemm_i8<2><<<gH, 256, SMEM_G>>>(qact, sact, qwp[L], swp[L],
                    outs[L], HH, HALF, bia[L], gam[L], bet[L], res[L]); break;
        default: gemm_i8<3><<<gH, 256, SMEM_G>>>(qact, sact, qwp[L], swp[L],
                    outs[L], HH, HALF, bia[L], gam[L], bet[L], res[L]); break;
        }
        cudaEventRecord(eg[2 * L + 1], 0);
        cudaStreamWaitEvent(s3, eg[2 * L + 1], 0);
        quant_act<<<QABH, 256, 0, s3>>>(outs[L], qact, sact, HALF);
        cudaEventRecord(eq[2 * L + 1], s3);
    }

    // ---- heads: fifs halves on main; lc on s2 (needs both qact halves) ----
    cudaStreamWaitEvent(0, evW[5], 0);
    cudaStreamWaitEvent(0, eq[8], 0);
    gemm_fifs_i8<<<gfiH, 256, SMEM_F>>>(qact, sact, qwfi, swfi, qwfs, swfs,
                                        x, 0, b_fi, b_fs, pse, psx, psf);
    cudaStreamWaitEvent(0, eq[9], 0);
    gemm_fifs_i8<<<gfiH, 256, SMEM_F>>>(qact, sact, qwfi, swfi, qwfs, swfs,
                                        x, HALF, b_fi, b_fs, pse, psx, psf);

    cudaStreamWaitEvent(s2, eq[8], 0);
    cudaStreamWaitEvent(s2, eq[9], 0);
    gemm_i8<0><<<glc, 256, SMEM_G, s2>>>(qact, sact, qwlc, swlc,
        lc, NLC, 0, b_lc, nullptr, nullptr, nullptr);
    cudaEventRecord(evLC, s2);

    cudaStreamWaitEvent(0, evLC, 0);
    sd_combine_kernel<<<BQ, 128>>>(pse, psx, psf, lc, out);
}